// round 11
// baseline (speedup 1.0000x reference)
#include <cuda_runtime.h>
#include <cuda_bf16.h>
#include <math.h>
#include <stdint.h>

#define Bn   8
#define Ln   9216
#define Cn   512
#define Hn   8
#define DK   64
#define HID  2048
#define Mrows (Bn*Ln)          // 73728
#define CKV  1024              // fused k|v width
#define CTXN (Bn*Hn*DK*DK)     // 262144 floats

// ---------------- scratch (device globals: no runtime allocation) ----------
__device__ float          g_xn  [Mrows*Cn];   // fp32 xn (transpose source)
__device__ float          g_xnT [Mrows*Cn];   // fp32 xn transposed (B,C,L)
__device__ __nv_bfloat16  g_xnb [Mrows*Cn];   // bf16 xn (GEMM A)
__device__ __nv_bfloat16  g_vnb [Mrows*Cn];   // bf16 vn (GEMM A)
__device__ __nv_bfloat16  g_qb  [Mrows*Cn];   // bf16 raw q
__device__ __nv_bfloat16  g_kvb [Mrows*CKV];  // bf16 fused [k | val] (raw)
__device__ float          g_kmax[Bn*Cn];
__device__ float          g_kinv[Bn*Cn];
__device__ float          g_ctx [CTXN];
__device__ __nv_bfloat16  g_aggT[Mrows*Cn];   // (B, L, C) bf16 (reproj B operand)
__device__ float          g_x1  [Mrows*Cn];   // x1 = reproj + br + xn^T + x (flat)
__device__ __nv_bfloat16  g_x1nb[Mrows*Cn];   // bf16 LN2 out (fc1 A)
__device__ __nv_bfloat16  g_h1b [Mrows*HID];  // bf16 gelu(fc1) (fc2 A)
// bf16 weights
__device__ __nv_bfloat16  g_wqb  [Cn*Cn];
__device__ __nv_bfloat16  g_wkvb [CKV*Cn];    // [wk ; wv]
__device__ __nv_bfloat16  g_wrb  [Cn*Cn];
__device__ __nv_bfloat16  g_f1b  [HID*Cn];
__device__ __nv_bfloat16  g_f2b  [Cn*HID];
__device__ float          g_bkv  [CKV];       // [bk ; bv]

// ---------------- asm helpers ------------------------------------------------
__device__ __forceinline__ uint32_t smem_u32(const void* p) {
    uint32_t a;
    asm("{ .reg .u64 t; cvta.to.shared.u64 t, %1; cvt.u32.u64 %0, t; }" : "=r"(a) : "l"(p));
    return a;
}
__device__ __forceinline__ void ldsm4(uint32_t* r, uint32_t a) {
    asm volatile("ldmatrix.sync.aligned.m8n8.x4.shared.b16 {%0,%1,%2,%3}, [%4];"
        : "=r"(r[0]), "=r"(r[1]), "=r"(r[2]), "=r"(r[3]) : "r"(a));
}
__device__ __forceinline__ void mma_bf16(float* c, const uint32_t* a, const uint32_t* b) {
    asm volatile("mma.sync.aligned.m16n8k16.row.col.f32.bf16.bf16.f32 "
        "{%0,%1,%2,%3}, {%4,%5,%6,%7}, {%8,%9}, {%0,%1,%2,%3};"
        : "+f"(c[0]), "+f"(c[1]), "+f"(c[2]), "+f"(c[3])
        : "r"(a[0]), "r"(a[1]), "r"(a[2]), "r"(a[3]), "r"(b[0]), "r"(b[1]));
}
__device__ __forceinline__ void cp16(uint32_t dst, const void* src) {
    asm volatile("cp.async.cg.shared.global [%0], [%1], 16;" :: "r"(dst), "l"(src));
}
#define CP_COMMIT() asm volatile("cp.async.commit_group;" ::: "memory")
#define CP_WAIT2()  asm volatile("cp.async.wait_group 2;" ::: "memory")

// smem tile geometry: rows of 32 bf16 (64B) padded to 80B -> conflict-free LDSM
#define ROWB   80
#define STG_A  (128*ROWB)          // 10240
#define STG    (2*STG_A)           // 20480 per stage
#define NST    4
#define SMEM_REQ (NST*STG)         // 81920  (2 CTAs/SM)

// ---------------- misc device helpers ---------------------------------------
__device__ __forceinline__ float gelu_exact(float x) {
    return 0.5f * x * (1.0f + erff(x * 0.70710678118654752f));
}

__device__ __forceinline__ float blockReduceSum256(float v, float* s8, int tid) {
    #pragma unroll
    for (int o = 16; o > 0; o >>= 1) v += __shfl_xor_sync(0xffffffffu, v, o);
    int lane = tid & 31, w = tid >> 5;
    if (lane == 0) s8[w] = v;
    __syncthreads();
    if (w == 0) {
        v = (lane < 8) ? s8[lane] : 0.f;
        #pragma unroll
        for (int o = 4; o > 0; o >>= 1) v += __shfl_xor_sync(0xffffffffu, v, o);
        if (lane == 0) s8[0] = v;
    }
    __syncthreads();
    float r = s8[0];
    __syncthreads();
    return r;
}

// ---------------- bf16 GEMM (NT): C[M,N] = A[M,K]·W[N,K]^T + epilogue -------
// CTA 128x128, warp tile 64x32 (8 warps), K-chunk 32, 4-stage cp.async,
// single __syncthreads per chunk (prefetch kt+3 after the barrier).
// EPI: 1 bias(n)+gelu -> bf16    2 bias(n)+res -> f32
//      4 bias(n) -> bf16
//      6 reproj fused: bias(m) + res(xnT flat) + res2(x flat), out f32
//        stride Ln, batch z  (writes x1 directly)
template<int EPI>
__global__ __launch_bounds__(256)
void gemm_bf16(const __nv_bfloat16* __restrict__ A, const __nv_bfloat16* __restrict__ W,
               const float* __restrict__ bias, const float* __restrict__ res,
               const float* __restrict__ res2,
               void* __restrict__ Cout, int Msz, int Nsz, int Ksz) {
    extern __shared__ char smem[];
    uint32_t sbase = smem_u32(smem);

    int tid = threadIdx.x;
    int wid = tid >> 5, lane = tid & 31;
    int m0 = blockIdx.y * 128, n0 = blockIdx.x * 128;
    int wm = (wid & 1) * 64, wn = (wid >> 1) * 32;
    int lrow = lane & 15;
    int lko  = (lane >> 4) * 16;

    const __nv_bfloat16* Aop = A;
    const __nv_bfloat16* Wop = W;
    const float* respZ = res;
    const float* res2Z = res2;
    float* CpF = (float*)Cout;
    __nv_bfloat16* CpH = (__nv_bfloat16*)Cout;
    if (EPI == 6) {
        size_t z = blockIdx.z;
        size_t zoff = z * (size_t)Cn * Ln;
        Wop   = W + z * (size_t)Ln * Cn;    // aggT batch slice [L, C] bf16
        respZ = res + zoff;                 // xnT (B,C,L) flat slice
        res2Z = res2 + zoff;                // x (flat-aligned) slice
        CpF   = (float*)Cout + zoff;
    }

    float acc[4][4][4];
    #pragma unroll
    for (int i = 0; i < 4; i++)
        #pragma unroll
        for (int j = 0; j < 4; j++)
            #pragma unroll
            for (int c = 0; c < 4; c++) acc[i][j][c] = 0.f;

    int arow = tid >> 2;          // 0..63
    int acol = tid & 3;           // 0..3 (16B chunks of 8 bf16)

    auto load_chunk = [&](int kt, int s) {
        uint32_t dA = sbase + s * STG;
        uint32_t dB = dA + STG_A;
        const __nv_bfloat16* ga = Aop + (size_t)(m0 + arow) * Ksz + kt * 32 + acol * 8;
        cp16(dA + (uint32_t)(arow * ROWB + acol * 16), ga);
        cp16(dA + (uint32_t)((arow + 64) * ROWB + acol * 16), ga + (size_t)64 * Ksz);
        const __nv_bfloat16* gb = Wop + (size_t)(n0 + arow) * Ksz + kt * 32 + acol * 8;
        cp16(dB + (uint32_t)(arow * ROWB + acol * 16), gb);
        cp16(dB + (uint32_t)((arow + 64) * ROWB + acol * 16), gb + (size_t)64 * Ksz);
        CP_COMMIT();
    };

    int nk = Ksz >> 5;
    load_chunk(0, 0);
    load_chunk(1, 1);
    load_chunk(2, 2);

    for (int kt = 0; kt < nk; kt++) {
        int s = kt & 3;
        CP_WAIT2();
        __syncthreads();
        // prefetch into slot (kt+3)&3, freed by the compute of iteration kt-1
        if (kt + 3 < nk) load_chunk(kt + 3, (kt + 3) & 3);
        else CP_COMMIT();           // keep group count uniform for wait_group

        uint32_t sA = sbase + s * STG;
        uint32_t sB = sA + STG_A;
        #pragma unroll
        for (int ks = 0; ks < 2; ks++) {
            uint32_t af[4][4], bf[2][4];
            #pragma unroll
            for (int mt = 0; mt < 4; mt++)
                ldsm4(af[mt], sA + (uint32_t)((wm + mt*16 + lrow) * ROWB + ks*32 + lko));
            #pragma unroll
            for (int g = 0; g < 2; g++)
                ldsm4(bf[g], sB + (uint32_t)((wn + g*16 + lrow) * ROWB + ks*32 + lko));
            #pragma unroll
            for (int mt = 0; mt < 4; mt++)
                #pragma unroll
                for (int nt = 0; nt < 4; nt++) {
                    uint32_t bb[2] = { bf[nt>>1][nt&1], bf[nt>>1][(nt&1) + 2] };
                    mma_bf16(acc[mt][nt], af[mt], bb);
                }
        }
    }

    // -------- epilogue (direct STG from accumulators)
    int rm = lane >> 2, cn = (lane & 3) * 2;
    #pragma unroll
    for (int mt = 0; mt < 4; mt++) {
        int m = m0 + wm + mt*16 + rm;
        float bm0 = 0.f, bm1 = 0.f;
        if (EPI == 6) { bm0 = bias[m]; bm1 = bias[m + 8]; }
        #pragma unroll
        for (int nt = 0; nt < 4; nt++) {
            int n = n0 + wn + nt*8 + cn;
            float* c = acc[mt][nt];
            if (EPI == 1) {
                float2 bb = *(const float2*)&bias[n];
                __nv_bfloat162 p0 = __floats2bfloat162_rn(gelu_exact(c[0]+bb.x), gelu_exact(c[1]+bb.y));
                __nv_bfloat162 p1 = __floats2bfloat162_rn(gelu_exact(c[2]+bb.x), gelu_exact(c[3]+bb.y));
                *(__nv_bfloat162*)&CpH[(size_t)m * Nsz + n]     = p0;
                *(__nv_bfloat162*)&CpH[(size_t)(m+8) * Nsz + n] = p1;
            } else if (EPI == 2) {
                float2 bb = *(const float2*)&bias[n];
                float2 r0 = *(const float2*)&respZ[(size_t)m * Nsz + n];
                float2 r1 = *(const float2*)&respZ[(size_t)(m+8) * Nsz + n];
                *(float2*)&CpF[(size_t)m * Nsz + n]     = make_float2(c[0]+bb.x+r0.x, c[1]+bb.y+r0.y);
                *(float2*)&CpF[(size_t)(m+8) * Nsz + n] = make_float2(c[2]+bb.x+r1.x, c[3]+bb.y+r1.y);
            } else if (EPI == 4) {
                float2 bb = *(const float2*)&bias[n];
                __nv_bfloat162 p0 = __floats2bfloat162_rn(c[0]+bb.x, c[1]+bb.y);
                __nv_bfloat162 p1 = __floats2bfloat162_rn(c[2]+bb.x, c[3]+bb.y);
                *(__nv_bfloat162*)&CpH[(size_t)m * Nsz + n]     = p0;
                *(__nv_bfloat162*)&CpH[(size_t)(m+8) * Nsz + n] = p1;
            } else {  // EPI == 6: bias(m) + xnT_flat + x_flat, write x1
                size_t f0 = (size_t)m * Ln + n;
                size_t f1 = (size_t)(m+8) * Ln + n;
                float2 t0 = *(const float2*)&respZ[f0];
                float2 t1 = *(const float2*)&respZ[f1];
                float2 u0 = *(const float2*)&res2Z[f0];
                float2 u1 = *(const float2*)&res2Z[f1];
                *(float2*)&CpF[f0] = make_float2(c[0]+bm0+t0.x+u0.x, c[1]+bm0+t0.y+u0.y);
                *(float2*)&CpF[f1] = make_float2(c[2]+bm1+t1.x+u1.x, c[3]+bm1+t1.y+u1.y);
            }
        }
    }
}

// ---------------- fused prep: all weight cvt + bias concat + ctx zero --------
// unit = 4 elements. Regions (in 4-elem units):
//   [0, 65536)          wq   -> wqb
//   [65536, 131072)     wk   -> wkvb[0:]
//   [131072, 196608)    wv   -> wkvb[Cn*Cn:]
//   [196608, 262144)    wr   -> wrb
//   [262144, 524288)    fc1  -> f1b
//   [524288, 786432)    fc2  -> f2b
//   [786432, 786688)    bk|bv -> bkv (f32)
//   [786688, 852224)    ctx zero (CTXN = 262144 floats = 65536 units)
#define PREP_UNITS 852224
__global__ void prep_kernel(const float* __restrict__ wq, const float* __restrict__ wk,
                            const float* __restrict__ wv, const float* __restrict__ wr,
                            const float* __restrict__ f1, const float* __restrict__ f2,
                            const float* __restrict__ bk, const float* __restrict__ bv,
                            __nv_bfloat16* __restrict__ wqb, __nv_bfloat16* __restrict__ wkvb,
                            __nv_bfloat16* __restrict__ wrb, __nv_bfloat16* __restrict__ f1b,
                            __nv_bfloat16* __restrict__ f2b, float* __restrict__ bkv,
                            float* __restrict__ ctx) {
    int u = blockIdx.x * blockDim.x + threadIdx.x;
    const float* src;
    __nv_bfloat16* dst;
    int off;
    if (u < 65536)        { src = wq; dst = wqb;  off = u; }
    else if (u < 131072)  { src = wk; dst = wkvb; off = u - 65536; }
    else if (u < 196608)  { src = wv; dst = wkvb + (size_t)Cn*Cn; off = u - 131072; }
    else if (u < 262144)  { src = wr; dst = wrb;  off = u - 196608; }
    else if (u < 524288)  { src = f1; dst = f1b;  off = u - 262144; }
    else if (u < 786432)  { src = f2; dst = f2b;  off = u - 524288; }
    else if (u < 786688)  {
        int i = (u - 786432) * 4;
        #pragma unroll
        for (int j = 0; j < 4; j++) {
            int k = i + j;
            bkv[k] = (k < Cn) ? bk[k] : bv[k - Cn];
        }
        return;
    } else if (u < 852224) {
        int i = (u - 786688) * 4;
        *(float4*)&ctx[i] = make_float4(0.f, 0.f, 0.f, 0.f);
        return;
    } else return;
    int i = off * 4;
    float4 v = *(const float4*)(src + i);
    *(__nv_bfloat162*)(dst + i)     = __floats2bfloat162_rn(v.x, v.y);
    *(__nv_bfloat162*)(dst + i + 2) = __floats2bfloat162_rn(v.z, v.w);
}

// ---------------- tiled transpose: xn (B,L,C) -> xnT (B,C,L) -----------------
__global__ void transpose_kernel(const float* __restrict__ in, float* __restrict__ out) {
    __shared__ float t[32][33];
    int z = blockIdx.z;
    int l0 = blockIdx.x * 32, c0 = blockIdx.y * 32;
    int tx = threadIdx.x, ty = threadIdx.y;
    const float* ip = in + (size_t)z * Ln * Cn;
    float* op = out + (size_t)z * Cn * Ln;
    #pragma unroll
    for (int k = 0; k < 4; k++)
        t[ty + 8*k][tx] = ip[(size_t)(l0 + ty + 8*k) * Cn + c0 + tx];
    __syncthreads();
    #pragma unroll
    for (int k = 0; k < 4; k++)
        op[(size_t)(c0 + ty + 8*k) * Ln + l0 + tx] = t[tx][ty + 8*k];
}

// ---------------- LayerNorm: bf16 out (+ optional f32 copy) ------------------
__global__ void ln_kernel(const float* __restrict__ in, const float* __restrict__ w,
                          const float* __restrict__ b, __nv_bfloat16* __restrict__ outb,
                          float* __restrict__ outf) {
    __shared__ float s8[8];
    int row = blockIdx.x, t = threadIdx.x;
    size_t base = (size_t)row * Cn;
    float v0 = in[base + t], v1 = in[base + t + 256];
    float mean = blockReduceSum256(v0 + v1, s8, t) * (1.0f / Cn);
    float d0 = v0 - mean, d1 = v1 - mean;
    float var = blockReduceSum256(d0*d0 + d1*d1, s8, t) * (1.0f / Cn);
    float rs = rsqrtf(var + 1e-5f);
    float o0 = d0 * rs * w[t]       + b[t];
    float o1 = d1 * rs * w[t + 256] + b[t + 256];
    outb[base + t]       = __float2bfloat16_rn(o0);
    outb[base + t + 256] = __float2bfloat16_rn(o1);
    if (outf) { outf[base + t] = o0; outf[base + t + 256] = o1; }
}

// ---------------- k stats: per (b, ck) online max + sumexp over L ------------
// 64 contiguous channels per block -> 128B coalesced rows.
__global__ void k_stats(const __nv_bfloat16* __restrict__ kvb,
                        float* __restrict__ kmax, float* __restrict__ kinv) {
    __shared__ float sm[4][64], ss[4][64];
    int tid = threadIdx.x;
    int c = tid & 63, w4 = tid >> 6;      // 0..3
    int ck = blockIdx.x * 64 + c;
    int b  = blockIdx.y;
    size_t base = (size_t)b * Ln * CKV + ck;

    float m = -1e30f, s = 0.f;
    for (int l = w4; l < Ln; l += 4) {
        float v = __bfloat162float(kvb[base + (size_t)l * CKV]);
        if (v > m) { s = s * __expf(m - v) + 1.0f; m = v; }
        else        s += __expf(v - m);
    }
    sm[w4][c] = m; ss[w4][c] = s;
    __syncthreads();
    if (w4 == 0) {
        #pragma unroll
        for (int t = 1; t < 4; t++) {
            float m2 = sm[t][c], s2 = ss[t][c];
            float M = fmaxf(m, m2);
            s = s * __expf(m - M) + s2 * __expf(m2 - M);
            m = M;
        }
        kmax[b * Cn + ck] = m;
        kinv[b * Cn + ck] = 1.0f / s;
    }
}

// ------- context[b,h,k,v] += sum_l softmax_l(k) * val (exp inline, bf16 in) --
__global__ __launch_bounds__(256)
void context_kernel(const __nv_bfloat16* __restrict__ kvb,
                    const float* __restrict__ kmax, const float* __restrict__ kinv,
                    float* __restrict__ ctx) {
    __shared__ float sK[8][64];
    __shared__ float sV[8][64];
    int b = blockIdx.z, h = blockIdx.y;
    int l0 = blockIdx.x * (Ln / 16);
    int tid = threadIdx.x;
    int tx = tid & 15, ty = tid >> 4;
    int li = tid >> 5, cc = tid & 31;

    float mA = kmax[b * Cn + h * DK + cc];
    float mB = kmax[b * Cn + h * DK + cc + 32];

    float acc[4][4] = {};
    for (int lc = l0; lc < l0 + Ln / 16; lc += 8) {
        size_t idx = ((size_t)(b * Ln + lc + li)) * CKV + h * DK + cc;
        sK[li][cc]      = __expf(__bfloat162float(kvb[idx])      - mA);
        sK[li][cc + 32] = __expf(__bfloat162float(kvb[idx + 32]) - mB);
        sV[li][cc]      = __bfloat162float(kvb[idx + Cn]);
        sV[li][cc + 32] = __bfloat162float(kvb[idx + Cn + 32]);
        __syncthreads();
        #pragma unroll
        for (int l = 0; l < 8; l++) {
            float kvv[4], vv[4];
            #pragma unroll
            for (int i = 0; i < 4; i++) { kvv[i] = sK[l][ty*4+i]; vv[i] = sV[l][tx*4+i]; }
            #pragma unroll
            for (int i = 0; i < 4; i++)
                #pragma unroll
                for (int j = 0; j < 4; j++) acc[i][j] = fmaf(kvv[i], vv[j], acc[i][j]);
        }
        __syncthreads();
    }
    size_t cb = (size_t)(b * Hn + h) * DK * DK;
    #pragma unroll
    for (int i = 0; i < 4; i++) {
        float zi = kinv[b * Cn + h * DK + ty*4 + i];
        #pragma unroll
        for (int j = 0; j < 4; j++)
            atomicAdd(&ctx[cb + (size_t)(ty*4+i) * DK + tx*4+j], acc[i][j] * zi);
    }
}

// ---- aggT[b, l, h*64+v] = sum_k ctx[b,h,k,v] * softmax_k(q[b,l,h,:]) -------
__global__ __launch_bounds__(256)
void agg_kernel(const __nv_bfloat16* __restrict__ qb, const float* __restrict__ ctx,
                __nv_bfloat16* __restrict__ aggT) {
    __shared__ float sC[64][64];
    __shared__ float sQ[128][65];   // padded: conflict-free row access
    int b = blockIdx.z, h = blockIdx.y, l0 = blockIdx.x * 128;
    int tid = threadIdx.x;
    int tx = tid & 15, ty = tid >> 4;

    size_t cb = (size_t)(b * Hn + h) * DK * DK;
    for (int f = tid; f < 4096; f += 256) sC[f >> 6][f & 63] = ctx[cb + f];
    for (int f = tid; f < 8192; f += 256) {
        int l = f >> 6, kk = f & 63;
        sQ[l][kk] = __bfloat162float(qb[((size_t)(b * Ln + l0 + l)) * Cn + h * DK + kk]);
    }
    __syncthreads();

    // in-block q softmax over the 64 channels of this head (2 threads/row)
    {
        int r = tid >> 1;
        int off = (tid & 1) * 32;
        float m = -1e30f;
        #pragma unroll
        for (int j = 0; j < 32; j++) m = fmaxf(m, sQ[r][off + j]);
        m = fmaxf(m, __shfl_xor_sync(0xffffffffu, m, 1));
        float s = 0.f;
        #pragma unroll
        for (int j = 0; j < 32; j++) {
            float e = __expf(sQ[r][off + j] - m);
            sQ[r][off + j] = e;
            s += e;
        }
        s += __shfl_xor_sync(0xffffffffu, s, 1);
        float inv = 1.0f / s;
        #pragma unroll
        for (int j = 0; j < 32; j++) sQ[r][off + j] *= inv;
    }
    __syncthreads();

    float acc[4][8] = {};
    #pragma unroll
    for (int k = 0; k < 64; k++) {
        float cv[4], qv[8];
        #pragma unroll
        for (int i = 0; i < 4; i++) cv[i] = sC[k][tx*4+i];
        #pragma unroll
        for (int j = 0; j < 8; j++) qv[j] = sQ[ty*8+j][k];
        #pragma unroll
        for (int i = 0; i < 4; i++)
            #pragma unroll
            for (int j = 0; j < 8; j++) acc[i][j] = fmaf(cv[i], qv[j], acc[i][j]);
    }
    #pragma unroll
    for (int j = 0; j < 8; j++) {
        size_t ob = ((size_t)(b * Ln + l0 + ty*8 + j)) * Cn + h * DK + tx*4;
        *(__nv_bfloat162*)&aggT[ob]     = __floats2bfloat162_rn(acc[0][j], acc[1][j]);
        *(__nv_bfloat162*)&aggT[ob + 2] = __floats2bfloat162_rn(acc[2][j], acc[3][j]);
    }
}

// ---------------- host launcher ---------------------------------------------
extern "C" void kernel_launch(void* const* d_in, const int* in_sizes, int n_in,
                              void* d_out, int out_size) {
    (void)in_sizes; (void)n_in; (void)out_size;
    const float* x     = (const float*)d_in[0];
    const float* v     = (const float*)d_in[1];
    const float* ln1_w = (const float*)d_in[4];
    const float* ln1_b = (const float*)d_in[5];
    const float* lnv_w = (const float*)d_in[6];
    const float* lnv_b = (const float*)d_in[7];
    const float* ln2_w = (const float*)d_in[8];
    const float* ln2_b = (const float*)d_in[9];
    const float* wq    = (const float*)d_in[10];
    const float* bq    = (const float*)d_in[11];
    const float* wk    = (const float*)d_in[12];
    const float* bk    = (const float*)d_in[13];
    const float* wv    = (const float*)d_in[14];
    const float* bv    = (const float*)d_in[15];
    const float* wr    = (const float*)d_in[16];
    const float* br    = (const float*)d_in[17];
    const float* fc1_w = (const float*)d_in[18];
    const float* fc1_b = (const float*)d_in[19];
    const float* fc2_w = (const float*)d_in[20];
    const float* fc2_b = (const float*)d_in[21];
    float* out = (float*)d_out;

    float *p_xn, *p_xnT, *p_kmax, *p_kinv, *p_ctx, *p_x1, *p_bkv;
    __nv_bfloat16 *p_xnb, *p_vnb, *p_qb, *p_kvb, *p_aggT, *p_x1nb, *p_h1b;
    __nv_bfloat16 *p_wqb, *p_wkvb, *p_wrb, *p_f1b, *p_f2b;
    cudaGetSymbolAddress((void**)&p_xn,  g_xn);
    cudaGetSymbolAddress((void**)&p_xnT, g_xnT);
    cudaGetSymbolAddress((void**)&p_xnb, g_xnb);
    cudaGetSymbolAddress((void**)&p_vnb, g_vnb);
    cudaGetSymbolAddress((void**)&p_qb,  g_qb);
    cudaGetSymbolAddress((void**)&p_kvb, g_kvb);
    cudaGetSymbolAddress((void**)&p_kmax,g_kmax);
    cudaGetSymbolAddress((void**)&p_kinv,g_kinv);
    cudaGetSymbolAddress((void**)&p_ctx, g_ctx);
    cudaGetSymbolAddress((void**)&p_aggT,g_aggT);
    cudaGetSymbolAddress((void**)&p_x1,  g_x1);
    cudaGetSymbolAddress((void**)&p_x1nb,g_x1nb);
    cudaGetSymbolAddress((void**)&p_h1b, g_h1b);
    cudaGetSymbolAddress((void**)&p_wqb, g_wqb);
    cudaGetSymbolAddress((void**)&p_wkvb,g_wkvb);
    cudaGetSymbolAddress((void**)&p_wrb, g_wrb);
    cudaGetSymbolAddress((void**)&p_f1b, g_f1b);
    cudaGetSymbolAddress((void**)&p_f2b, g_f2b);
    cudaGetSymbolAddress((void**)&p_bkv, g_bkv);

    cudaFuncSetAttribute(gemm_bf16<1>, cudaFuncAttributeMaxDynamicSharedMemorySize, SMEM_REQ);
    cudaFuncSetAttribute(gemm_bf16<2>, cudaFuncAttributeMaxDynamicSharedMemorySize, SMEM_REQ);
    cudaFuncSetAttribute(gemm_bf16<4>, cudaFuncAttributeMaxDynamicSharedMemorySize, SMEM_REQ);
    cudaFuncSetAttribute(gemm_bf16<6>, cudaFuncAttributeMaxDynamicSharedMemorySize, SMEM_REQ);

    // 0) fused prep: all weight conversions + bias concat + FULL ctx zero
    prep_kernel<<<(PREP_UNITS + 255)/256, 256>>>(wq, wk, wv, wr, fc1_w, fc2_w, bk, bv,
                                                 p_wqb, p_wkvb, p_wrb, p_f1b, p_f2b,
                                                 p_bkv, p_ctx);

    // 1) LayerNorms (+ xn transpose for the flat residual)
    ln_kernel<<<Mrows, 256>>>(x, ln1_w, ln1_b, p_xnb, p_xn);
    ln_kernel<<<Mrows, 256>>>(v, lnv_w, lnv_b, p_vnb, nullptr);
    transpose_kernel<<<dim3(Ln/32, Cn/32, Bn), dim3(32, 8)>>>(p_xn, p_xnT);

    // 2) projections: q (N=512, bf16 out), fused k|v (N=1024, bf16 out)
    gemm_bf16<4><<<dim3(Cn / 128, Mrows / 128), 256, SMEM_REQ>>>(
        p_xnb, p_wqb, bq, nullptr, nullptr, p_qb, Mrows, Cn, Cn);
    gemm_bf16<4><<<dim3(CKV / 128, Mrows / 128), 256, SMEM_REQ>>>(
        p_vnb, p_wkvb, p_bkv, nullptr, nullptr, p_kvb, Mrows, CKV, Cn);

    // 3) k softmax stats (single pass, coalesced); exp applied inline in context
    k_stats<<<dim3(Cn / 64, Bn), 256>>>(p_kvb, p_kmax, p_kinv);

    // 4) context = softmax_l(k)^T @ val
    context_kernel<<<dim3(16, Hn, Bn), 256>>>(p_kvb, p_kmax, p_kinv, p_ctx);

    // 5) aggT = (ctx^T @ softmax(q))^T  -> (B, L, C) bf16
    agg_kernel<<<dim3(Ln / 128, Hn, Bn), 256>>>(p_qb, p_ctx, p_aggT);

    // 6) reproj fused: x1 = wr·aggT + br + xnT + x   (writes x1 directly)
    gemm_bf16<6><<<dim3(Ln / 128, Cn / 128, Bn), 256, SMEM_REQ>>>(
        p_wrb, p_aggT, br, p_xnT, x, p_x1, Cn, Ln, Cn);

    // 7) x1n = LN(x1) (bf16)
    ln_kernel<<<Mrows, 256>>>(p_x1, ln2_w, ln2_b, p_x1nb, nullptr);

    // 8) MLP
    gemm_bf16<1><<<dim3(HID / 128, Mrows / 128), 256, SMEM_REQ>>>(
        p_x1nb, p_f1b, fc1_b, nullptr, nullptr, p_h1b, Mrows, HID, Cn);
    gemm_bf16<2><<<dim3(Cn / 128, Mrows / 128), 256, SMEM_REQ>>>(
        p_h1b, p_f2b, fc2_b, p_x1, nullptr, out, Mrows, Cn, HID);
}

// round 12
// speedup vs baseline: 1.0230x; 1.0230x over previous
#include <cuda_runtime.h>
#include <cuda_bf16.h>
#include <math.h>
#include <stdint.h>

#define Bn   8
#define Ln   9216
#define Cn   512
#define Hn   8
#define DK   64
#define HID  2048
#define Mrows (Bn*Ln)          // 73728
#define CKV  1024              // fused k|v width
#define CTXN (Bn*Hn*DK*DK)     // 262144 floats

// ---------------- scratch (device globals: no runtime allocation) ----------
__device__ float          g_xnT [Mrows*Cn];   // fp32 xn transposed (B,C,L)
__device__ __nv_bfloat16  g_xnb [Mrows*Cn];   // bf16 xn (GEMM A)
__device__ __nv_bfloat16  g_vnb [Mrows*Cn];   // bf16 vn (GEMM A)
__device__ __nv_bfloat16  g_qb  [Mrows*Cn];   // bf16 raw q
__device__ __nv_bfloat16  g_kvb [Mrows*CKV];  // bf16 fused [k | val] (raw)
__device__ float          g_kmax[Bn*Cn];
__device__ float          g_kinv[Bn*Cn];
__device__ float          g_ctx [CTXN];
__device__ __nv_bfloat16  g_aggT[Mrows*Cn];   // (B, L, C) bf16 (reproj B operand)
__device__ float          g_x1  [Mrows*Cn];   // x1 = reproj + br + xn^T + x (flat)
__device__ __nv_bfloat16  g_x1nb[Mrows*Cn];   // bf16 LN2 out (fc1 A)
__device__ __nv_bfloat16  g_h1b [Mrows*HID];  // bf16 gelu(fc1) (fc2 A)
// bf16 weights
__device__ __nv_bfloat16  g_wqb  [Cn*Cn];
__device__ __nv_bfloat16  g_wkvb [CKV*Cn];    // [wk ; wv]
__device__ __nv_bfloat16  g_wrb  [Cn*Cn];
__device__ __nv_bfloat16  g_f1b  [HID*Cn];
__device__ __nv_bfloat16  g_f2b  [Cn*HID];
__device__ float          g_bkv  [CKV];       // [bk ; bv]

// ---------------- asm helpers ------------------------------------------------
__device__ __forceinline__ uint32_t smem_u32(const void* p) {
    uint32_t a;
    asm("{ .reg .u64 t; cvta.to.shared.u64 t, %1; cvt.u32.u64 %0, t; }" : "=r"(a) : "l"(p));
    return a;
}
__device__ __forceinline__ void ldsm4(uint32_t* r, uint32_t a) {
    asm volatile("ldmatrix.sync.aligned.m8n8.x4.shared.b16 {%0,%1,%2,%3}, [%4];"
        : "=r"(r[0]), "=r"(r[1]), "=r"(r[2]), "=r"(r[3]) : "r"(a));
}
__device__ __forceinline__ void mma_bf16(float* c, const uint32_t* a, const uint32_t* b) {
    asm volatile("mma.sync.aligned.m16n8k16.row.col.f32.bf16.bf16.f32 "
        "{%0,%1,%2,%3}, {%4,%5,%6,%7}, {%8,%9}, {%0,%1,%2,%3};"
        : "+f"(c[0]), "+f"(c[1]), "+f"(c[2]), "+f"(c[3])
        : "r"(a[0]), "r"(a[1]), "r"(a[2]), "r"(a[3]), "r"(b[0]), "r"(b[1]));
}
__device__ __forceinline__ void cp16(uint32_t dst, const void* src) {
    asm volatile("cp.async.cg.shared.global [%0], [%1], 16;" :: "r"(dst), "l"(src));
}
#define CP_COMMIT() asm volatile("cp.async.commit_group;" ::: "memory")
#define CP_WAIT2()  asm volatile("cp.async.wait_group 2;" ::: "memory")

// smem tile geometry: rows of 32 bf16 (64B) padded to 80B -> conflict-free LDSM
#define ROWB   80
#define STG_A  (128*ROWB)          // 10240
#define STG    (2*STG_A)           // 20480 per stage
#define NST    4
#define SMEM_REQ (NST*STG)         // 81920  (2 CTAs/SM)

// ---------------- misc device helpers ---------------------------------------
__device__ __forceinline__ float gelu_exact(float x) {
    return 0.5f * x * (1.0f + erff(x * 0.70710678118654752f));
}

__device__ __forceinline__ float blockReduceSum256(float v, float* s8, int tid) {
    #pragma unroll
    for (int o = 16; o > 0; o >>= 1) v += __shfl_xor_sync(0xffffffffu, v, o);
    int lane = tid & 31, w = tid >> 5;
    if (lane == 0) s8[w] = v;
    __syncthreads();
    if (w == 0) {
        v = (lane < 8) ? s8[lane] : 0.f;
        #pragma unroll
        for (int o = 4; o > 0; o >>= 1) v += __shfl_xor_sync(0xffffffffu, v, o);
        if (lane == 0) s8[0] = v;
    }
    __syncthreads();
    float r = s8[0];
    __syncthreads();
    return r;
}

// ---------------- bf16 GEMM (NT): C[M,N] = A[M,K]·W[N,K]^T + epilogue -------
// CTA 128x128, warp tile 64x32 (8 warps), K-chunk 32, 4-stage cp.async,
// single __syncthreads per chunk (prefetch kt+3 after the barrier).
// EPI: 1 bias(n)+gelu -> bf16    2 bias(n)+res -> f32
//      4 bias(n) -> bf16
//      6 reproj fused: bias(m) + res(xnT flat) + res2(x flat), out f32
//        stride Ln, batch z  (writes x1 directly)
template<int EPI>
__global__ __launch_bounds__(256)
void gemm_bf16(const __nv_bfloat16* __restrict__ A, const __nv_bfloat16* __restrict__ W,
               const float* __restrict__ bias, const float* __restrict__ res,
               const float* __restrict__ res2,
               void* __restrict__ Cout, int Msz, int Nsz, int Ksz) {
    extern __shared__ char smem[];
    uint32_t sbase = smem_u32(smem);

    int tid = threadIdx.x;
    int wid = tid >> 5, lane = tid & 31;
    int m0 = blockIdx.y * 128, n0 = blockIdx.x * 128;
    int wm = (wid & 1) * 64, wn = (wid >> 1) * 32;
    int lrow = lane & 15;
    int lko  = (lane >> 4) * 16;

    const __nv_bfloat16* Aop = A;
    const __nv_bfloat16* Wop = W;
    const float* respZ = res;
    const float* res2Z = res2;
    float* CpF = (float*)Cout;
    __nv_bfloat16* CpH = (__nv_bfloat16*)Cout;
    if (EPI == 6) {
        size_t z = blockIdx.z;
        size_t zoff = z * (size_t)Cn * Ln;
        Wop   = W + z * (size_t)Ln * Cn;    // aggT batch slice [L, C] bf16
        respZ = res + zoff;                 // xnT (B,C,L) flat slice
        res2Z = res2 + zoff;                // x (flat-aligned) slice
        CpF   = (float*)Cout + zoff;
    }

    float acc[4][4][4];
    #pragma unroll
    for (int i = 0; i < 4; i++)
        #pragma unroll
        for (int j = 0; j < 4; j++)
            #pragma unroll
            for (int c = 0; c < 4; c++) acc[i][j][c] = 0.f;

    int arow = tid >> 2;          // 0..63
    int acol = tid & 3;           // 0..3 (16B chunks of 8 bf16)

    auto load_chunk = [&](int kt, int s) {
        uint32_t dA = sbase + s * STG;
        uint32_t dB = dA + STG_A;
        const __nv_bfloat16* ga = Aop + (size_t)(m0 + arow) * Ksz + kt * 32 + acol * 8;
        cp16(dA + (uint32_t)(arow * ROWB + acol * 16), ga);
        cp16(dA + (uint32_t)((arow + 64) * ROWB + acol * 16), ga + (size_t)64 * Ksz);
        const __nv_bfloat16* gb = Wop + (size_t)(n0 + arow) * Ksz + kt * 32 + acol * 8;
        cp16(dB + (uint32_t)(arow * ROWB + acol * 16), gb);
        cp16(dB + (uint32_t)((arow + 64) * ROWB + acol * 16), gb + (size_t)64 * Ksz);
        CP_COMMIT();
    };

    int nk = Ksz >> 5;
    load_chunk(0, 0);
    load_chunk(1, 1);
    load_chunk(2, 2);

    for (int kt = 0; kt < nk; kt++) {
        int s = kt & 3;
        CP_WAIT2();
        __syncthreads();
        // prefetch into slot (kt+3)&3, freed by the compute of iteration kt-1
        if (kt + 3 < nk) load_chunk(kt + 3, (kt + 3) & 3);
        else CP_COMMIT();           // keep group count uniform for wait_group

        uint32_t sA = sbase + s * STG;
        uint32_t sB = sA + STG_A;
        #pragma unroll
        for (int ks = 0; ks < 2; ks++) {
            uint32_t af[4][4], bf[2][4];
            #pragma unroll
            for (int mt = 0; mt < 4; mt++)
                ldsm4(af[mt], sA + (uint32_t)((wm + mt*16 + lrow) * ROWB + ks*32 + lko));
            #pragma unroll
            for (int g = 0; g < 2; g++)
                ldsm4(bf[g], sB + (uint32_t)((wn + g*16 + lrow) * ROWB + ks*32 + lko));
            #pragma unroll
            for (int mt = 0; mt < 4; mt++)
                #pragma unroll
                for (int nt = 0; nt < 4; nt++) {
                    uint32_t bb[2] = { bf[nt>>1][nt&1], bf[nt>>1][(nt&1) + 2] };
                    mma_bf16(acc[mt][nt], af[mt], bb);
                }
        }
    }

    // -------- epilogue (direct STG from accumulators)
    int rm = lane >> 2, cn = (lane & 3) * 2;
    #pragma unroll
    for (int mt = 0; mt < 4; mt++) {
        int m = m0 + wm + mt*16 + rm;
        float bm0 = 0.f, bm1 = 0.f;
        if (EPI == 6) { bm0 = bias[m]; bm1 = bias[m + 8]; }
        #pragma unroll
        for (int nt = 0; nt < 4; nt++) {
            int n = n0 + wn + nt*8 + cn;
            float* c = acc[mt][nt];
            if (EPI == 1) {
                float2 bb = *(const float2*)&bias[n];
                __nv_bfloat162 p0 = __floats2bfloat162_rn(gelu_exact(c[0]+bb.x), gelu_exact(c[1]+bb.y));
                __nv_bfloat162 p1 = __floats2bfloat162_rn(gelu_exact(c[2]+bb.x), gelu_exact(c[3]+bb.y));
                *(__nv_bfloat162*)&CpH[(size_t)m * Nsz + n]     = p0;
                *(__nv_bfloat162*)&CpH[(size_t)(m+8) * Nsz + n] = p1;
            } else if (EPI == 2) {
                float2 bb = *(const float2*)&bias[n];
                float2 r0 = *(const float2*)&respZ[(size_t)m * Nsz + n];
                float2 r1 = *(const float2*)&respZ[(size_t)(m+8) * Nsz + n];
                *(float2*)&CpF[(size_t)m * Nsz + n]     = make_float2(c[0]+bb.x+r0.x, c[1]+bb.y+r0.y);
                *(float2*)&CpF[(size_t)(m+8) * Nsz + n] = make_float2(c[2]+bb.x+r1.x, c[3]+bb.y+r1.y);
            } else if (EPI == 4) {
                float2 bb = *(const float2*)&bias[n];
                __nv_bfloat162 p0 = __floats2bfloat162_rn(c[0]+bb.x, c[1]+bb.y);
                __nv_bfloat162 p1 = __floats2bfloat162_rn(c[2]+bb.x, c[3]+bb.y);
                *(__nv_bfloat162*)&CpH[(size_t)m * Nsz + n]     = p0;
                *(__nv_bfloat162*)&CpH[(size_t)(m+8) * Nsz + n] = p1;
            } else {  // EPI == 6: bias(m) + xnT_flat + x_flat, write x1
                size_t f0 = (size_t)m * Ln + n;
                size_t f1 = (size_t)(m+8) * Ln + n;
                float2 t0 = *(const float2*)&respZ[f0];
                float2 t1 = *(const float2*)&respZ[f1];
                float2 u0 = *(const float2*)&res2Z[f0];
                float2 u1 = *(const float2*)&res2Z[f1];
                *(float2*)&CpF[f0] = make_float2(c[0]+bm0+t0.x+u0.x, c[1]+bm0+t0.y+u0.y);
                *(float2*)&CpF[f1] = make_float2(c[2]+bm1+t1.x+u1.x, c[3]+bm1+t1.y+u1.y);
            }
        }
    }
}

// ---------------- fused prep: all weight cvt + bias concat + ctx zero --------
// unit = 4 elements. Regions (in 4-elem units):
//   [0, 65536)          wq   -> wqb
//   [65536, 131072)     wk   -> wkvb[0:]
//   [131072, 196608)    wv   -> wkvb[Cn*Cn:]
//   [196608, 262144)    wr   -> wrb
//   [262144, 524288)    fc1  -> f1b
//   [524288, 786432)    fc2  -> f2b
//   [786432, 786688)    bk|bv -> bkv (f32)
//   [786688, 852224)    ctx zero (CTXN = 262144 floats = 65536 units)
#define PREP_UNITS 852224
__global__ void prep_kernel(const float* __restrict__ wq, const float* __restrict__ wk,
                            const float* __restrict__ wv, const float* __restrict__ wr,
                            const float* __restrict__ f1, const float* __restrict__ f2,
                            const float* __restrict__ bk, const float* __restrict__ bv,
                            __nv_bfloat16* __restrict__ wqb, __nv_bfloat16* __restrict__ wkvb,
                            __nv_bfloat16* __restrict__ wrb, __nv_bfloat16* __restrict__ f1b,
                            __nv_bfloat16* __restrict__ f2b, float* __restrict__ bkv,
                            float* __restrict__ ctx) {
    int u = blockIdx.x * blockDim.x + threadIdx.x;
    const float* src;
    __nv_bfloat16* dst;
    int off;
    if (u < 65536)        { src = wq; dst = wqb;  off = u; }
    else if (u < 131072)  { src = wk; dst = wkvb; off = u - 65536; }
    else if (u < 196608)  { src = wv; dst = wkvb + (size_t)Cn*Cn; off = u - 131072; }
    else if (u < 262144)  { src = wr; dst = wrb;  off = u - 196608; }
    else if (u < 524288)  { src = f1; dst = f1b;  off = u - 262144; }
    else if (u < 786432)  { src = f2; dst = f2b;  off = u - 524288; }
    else if (u < 786688)  {
        int i = (u - 786432) * 4;
        #pragma unroll
        for (int j = 0; j < 4; j++) {
            int k = i + j;
            bkv[k] = (k < Cn) ? bk[k] : bv[k - Cn];
        }
        return;
    } else if (u < 852224) {
        int i = (u - 786688) * 4;
        *(float4*)&ctx[i] = make_float4(0.f, 0.f, 0.f, 0.f);
        return;
    } else return;
    int i = off * 4;
    float4 v = *(const float4*)(src + i);
    *(__nv_bfloat162*)(dst + i)     = __floats2bfloat162_rn(v.x, v.y);
    *(__nv_bfloat162*)(dst + i + 2) = __floats2bfloat162_rn(v.z, v.w);
}

// ------- fused LN1(x) + transpose: writes xnb (bf16, (B,L,C)) + xnT (f32, (B,C,L))
// One block = 32 consecutive rows (within one batch; Ln % 32 == 0).
// Warp w handles row l0+w: warp-shuffle LN stats over 512 cols.
// Normalized f32 rows parked in smem (pitch 513 -> conflict-free column reads),
// then transposed 128B-coalesced stores into xnT.
#define LNX_PITCH 513
#define LNX_SMEM  (32 * LNX_PITCH * 4)   // 65,664 B
__global__ __launch_bounds__(1024)
void ln_x_kernel(const float* __restrict__ in, const float* __restrict__ w,
                 const float* __restrict__ b, __nv_bfloat16* __restrict__ outb,
                 float* __restrict__ outT) {
    extern __shared__ float s[];
    int tid = threadIdx.x;
    int wrp = tid >> 5, lane = tid & 31;
    int row0 = blockIdx.x * 32;
    int row = row0 + wrp;
    size_t base = (size_t)row * Cn;

    float4 v[4];
    float sum = 0.f;
    #pragma unroll
    for (int j = 0; j < 4; j++) {
        v[j] = *(const float4*)(in + base + lane * 4 + j * 128);
        sum += v[j].x + v[j].y + v[j].z + v[j].w;
    }
    #pragma unroll
    for (int o = 16; o > 0; o >>= 1) sum += __shfl_xor_sync(0xffffffffu, sum, o);
    float mean = sum * (1.0f / Cn);
    float vs = 0.f;
    #pragma unroll
    for (int j = 0; j < 4; j++) {
        float d0 = v[j].x - mean, d1 = v[j].y - mean, d2 = v[j].z - mean, d3 = v[j].w - mean;
        vs += d0*d0 + d1*d1 + d2*d2 + d3*d3;
    }
    #pragma unroll
    for (int o = 16; o > 0; o >>= 1) vs += __shfl_xor_sync(0xffffffffu, vs, o);
    float rs = rsqrtf(vs * (1.0f / Cn) + 1e-5f);

    float* srow = s + wrp * LNX_PITCH;
    #pragma unroll
    for (int j = 0; j < 4; j++) {
        int c = lane * 4 + j * 128;
        float4 ww = *(const float4*)(w + c);
        float4 bb = *(const float4*)(b + c);
        float o0 = (v[j].x - mean) * rs * ww.x + bb.x;
        float o1 = (v[j].y - mean) * rs * ww.y + bb.y;
        float o2 = (v[j].z - mean) * rs * ww.z + bb.z;
        float o3 = (v[j].w - mean) * rs * ww.w + bb.w;
        *(__nv_bfloat162*)(outb + base + c)     = __floats2bfloat162_rn(o0, o1);
        *(__nv_bfloat162*)(outb + base + c + 2) = __floats2bfloat162_rn(o2, o3);
        srow[c] = o0; srow[c+1] = o1; srow[c+2] = o2; srow[c+3] = o3;
    }
    __syncthreads();

    // transposed write: 4096 float4 units; idx = it*1024 + tid; c = idx>>3, p = idx&7
    int bz = row0 / Ln;
    int lb = row0 - bz * Ln;
    float* op = outT + (size_t)bz * Cn * Ln + lb;
    #pragma unroll
    for (int it = 0; it < 4; it++) {
        int idx = it * 1024 + tid;
        int c = idx >> 3, p = idx & 7;
        int l = p * 4;
        float4 ov = make_float4(s[(l+0) * LNX_PITCH + c], s[(l+1) * LNX_PITCH + c],
                                s[(l+2) * LNX_PITCH + c], s[(l+3) * LNX_PITCH + c]);
        *(float4*)(op + (size_t)c * Ln + l) = ov;
    }
}

// ---------------- LayerNorm (plain, bf16 out) --------------------------------
__global__ void ln_kernel(const float* __restrict__ in, const float* __restrict__ w,
                          const float* __restrict__ b, __nv_bfloat16* __restrict__ outb) {
    __shared__ float s8[8];
    int row = blockIdx.x, t = threadIdx.x;
    size_t base = (size_t)row * Cn;
    float v0 = in[base + t], v1 = in[base + t + 256];
    float mean = blockReduceSum256(v0 + v1, s8, t) * (1.0f / Cn);
    float d0 = v0 - mean, d1 = v1 - mean;
    float var = blockReduceSum256(d0*d0 + d1*d1, s8, t) * (1.0f / Cn);
    float rs = rsqrtf(var + 1e-5f);
    outb[base + t]       = __float2bfloat16_rn(d0 * rs * w[t]       + b[t]);
    outb[base + t + 256] = __float2bfloat16_rn(d1 * rs * w[t + 256] + b[t + 256]);
}

// ---------------- k stats: per (b, ck) online max + sumexp over L ------------
// 64 contiguous channels per block -> 128B coalesced rows.
__global__ void k_stats(const __nv_bfloat16* __restrict__ kvb,
                        float* __restrict__ kmax, float* __restrict__ kinv) {
    __shared__ float sm[4][64], ss[4][64];
    int tid = threadIdx.x;
    int c = tid & 63, w4 = tid >> 6;      // 0..3
    int ck = blockIdx.x * 64 + c;
    int b  = blockIdx.y;
    size_t base = (size_t)b * Ln * CKV + ck;

    float m = -1e30f, s = 0.f;
    for (int l = w4; l < Ln; l += 4) {
        float v = __bfloat162float(kvb[base + (size_t)l * CKV]);
        if (v > m) { s = s * __expf(m - v) + 1.0f; m = v; }
        else        s += __expf(v - m);
    }
    sm[w4][c] = m; ss[w4][c] = s;
    __syncthreads();
    if (w4 == 0) {
        #pragma unroll
        for (int t = 1; t < 4; t++) {
            float m2 = sm[t][c], s2 = ss[t][c];
            float M = fmaxf(m, m2);
            s = s * __expf(m - M) + s2 * __expf(m2 - M);
            m = M;
        }
        kmax[b * Cn + ck] = m;
        kinv[b * Cn + ck] = 1.0f / s;
    }
}

// ------- context[b,h,k,v] += sum_l softmax_l(k) * val (exp inline, bf16 in) --
__global__ __launch_bounds__(256)
void context_kernel(const __nv_bfloat16* __restrict__ kvb,
                    const float* __restrict__ kmax, const float* __restrict__ kinv,
                    float* __restrict__ ctx) {
    __shared__ float sK[8][64];
    __shared__ float sV[8][64];
    int b = blockIdx.z, h = blockIdx.y;
    int l0 = blockIdx.x * (Ln / 16);
    int tid = threadIdx.x;
    int tx = tid & 15, ty = tid >> 4;
    int li = tid >> 5, cc = tid & 31;

    float mA = kmax[b * Cn + h * DK + cc];
    float mB = kmax[b * Cn + h * DK + cc + 32];

    float acc[4][4] = {};
    for (int lc = l0; lc < l0 + Ln / 16; lc += 8) {
        size_t idx = ((size_t)(b * Ln + lc + li)) * CKV + h * DK + cc;
        sK[li][cc]      = __expf(__bfloat162float(kvb[idx])      - mA);
        sK[li][cc + 32] = __expf(__bfloat162float(kvb[idx + 32]) - mB);
        sV[li][cc]      = __bfloat162float(kvb[idx + Cn]);
        sV[li][cc + 32] = __bfloat162float(kvb[idx + Cn + 32]);
        __syncthreads();
        #pragma unroll
        for (int l = 0; l < 8; l++) {
            float kvv[4], vv[4];
            #pragma unroll
            for (int i = 0; i < 4; i++) { kvv[i] = sK[l][ty*4+i]; vv[i] = sV[l][tx*4+i]; }
            #pragma unroll
            for (int i = 0; i < 4; i++)
                #pragma unroll
                for (int j = 0; j < 4; j++) acc[i][j] = fmaf(kvv[i], vv[j], acc[i][j]);
        }
        __syncthreads();
    }
    size_t cb = (size_t)(b * Hn + h) * DK * DK;
    #pragma unroll
    for (int i = 0; i < 4; i++) {
        float zi = kinv[b * Cn + h * DK + ty*4 + i];
        #pragma unroll
        for (int j = 0; j < 4; j++)
            atomicAdd(&ctx[cb + (size_t)(ty*4+i) * DK + tx*4+j], acc[i][j] * zi);
    }
}

// ---- aggT[b, l, h*64+v] = sum_k ctx[b,h,k,v] * softmax_k(q[b,l,h,:]) -------
__global__ __launch_bounds__(256)
void agg_kernel(const __nv_bfloat16* __restrict__ qb, const float* __restrict__ ctx,
                __nv_bfloat16* __restrict__ aggT) {
    __shared__ float sC[64][64];
    __shared__ float sQ[128][65];   // padded: conflict-free row access
    int b = blockIdx.z, h = blockIdx.y, l0 = blockIdx.x * 128;
    int tid = threadIdx.x;
    int tx = tid & 15, ty = tid >> 4;

    size_t cb = (size_t)(b * Hn + h) * DK * DK;
    for (int f = tid; f < 4096; f += 256) sC[f >> 6][f & 63] = ctx[cb + f];
    for (int f = tid; f < 8192; f += 256) {
        int l = f >> 6, kk = f & 63;
        sQ[l][kk] = __bfloat162float(qb[((size_t)(b * Ln + l0 + l)) * Cn + h * DK + kk]);
    }
    __syncthreads();

    // in-block q softmax over the 64 channels of this head (2 threads/row)
    {
        int r = tid >> 1;
        int off = (tid & 1) * 32;
        float m = -1e30f;
        #pragma unroll
        for (int j = 0; j < 32; j++) m = fmaxf(m, sQ[r][off + j]);
        m = fmaxf(m, __shfl_xor_sync(0xffffffffu, m, 1));
        float s = 0.f;
        #pragma unroll
        for (int j = 0; j < 32; j++) {
            float e = __expf(sQ[r][off + j] - m);
            sQ[r][off + j] = e;
            s += e;
        }
        s += __shfl_xor_sync(0xffffffffu, s, 1);
        float inv = 1.0f / s;
        #pragma unroll
        for (int j = 0; j < 32; j++) sQ[r][off + j] *= inv;
    }
    __syncthreads();

    float acc[4][8] = {};
    #pragma unroll
    for (int k = 0; k < 64; k++) {
        float cv[4], qv[8];
        #pragma unroll
        for (int i = 0; i < 4; i++) cv[i] = sC[k][tx*4+i];
        #pragma unroll
        for (int j = 0; j < 8; j++) qv[j] = sQ[ty*8+j][k];
        #pragma unroll
        for (int i = 0; i < 4; i++)
            #pragma unroll
            for (int j = 0; j < 8; j++) acc[i][j] = fmaf(cv[i], qv[j], acc[i][j]);
    }
    #pragma unroll
    for (int j = 0; j < 8; j++) {
        size_t ob = ((size_t)(b * Ln + l0 + ty*8 + j)) * Cn + h * DK + tx*4;
        *(__nv_bfloat162*)&aggT[ob]     = __floats2bfloat162_rn(acc[0][j], acc[1][j]);
        *(__nv_bfloat162*)&aggT[ob + 2] = __floats2bfloat162_rn(acc[2][j], acc[3][j]);
    }
}

// ---------------- host launcher ---------------------------------------------
extern "C" void kernel_launch(void* const* d_in, const int* in_sizes, int n_in,
                              void* d_out, int out_size) {
    (void)in_sizes; (void)n_in; (void)out_size;
    const float* x     = (const float*)d_in[0];
    const float* v     = (const float*)d_in[1];
    const float* ln1_w = (const float*)d_in[4];
    const float* ln1_b = (const float*)d_in[5];
    const float* lnv_w = (const float*)d_in[6];
    const float* lnv_b = (const float*)d_in[7];
    const float* ln2_w = (const float*)d_in[8];
    const float* ln2_b = (const float*)d_in[9];
    const float* wq    = (const float*)d_in[10];
    const float* bq    = (const float*)d_in[11];
    const float* wk    = (const float*)d_in[12];
    const float* bk    = (const float*)d_in[13];
    const float* wv    = (const float*)d_in[14];
    const float* bv    = (const float*)d_in[15];
    const float* wr    = (const float*)d_in[16];
    const float* br    = (const float*)d_in[17];
    const float* fc1_w = (const float*)d_in[18];
    const float* fc1_b = (const float*)d_in[19];
    const float* fc2_w = (const float*)d_in[20];
    const float* fc2_b = (const float*)d_in[21];
    float* out = (float*)d_out;

    float *p_xnT, *p_kmax, *p_kinv, *p_ctx, *p_x1, *p_bkv;
    __nv_bfloat16 *p_xnb, *p_vnb, *p_qb, *p_kvb, *p_aggT, *p_x1nb, *p_h1b;
    __nv_bfloat16 *p_wqb, *p_wkvb, *p_wrb, *p_f1b, *p_f2b;
    cudaGetSymbolAddress((void**)&p_xnT, g_xnT);
    cudaGetSymbolAddress((void**)&p_xnb, g_xnb);
    cudaGetSymbolAddress((void**)&p_vnb, g_vnb);
    cudaGetSymbolAddress((void**)&p_qb,  g_qb);
    cudaGetSymbolAddress((void**)&p_kvb, g_kvb);
    cudaGetSymbolAddress((void**)&p_kmax,g_kmax);
    cudaGetSymbolAddress((void**)&p_kinv,g_kinv);
    cudaGetSymbolAddress((void**)&p_ctx, g_ctx);
    cudaGetSymbolAddress((void**)&p_aggT,g_aggT);
    cudaGetSymbolAddress((void**)&p_x1,  g_x1);
    cudaGetSymbolAddress((void**)&p_x1nb,g_x1nb);
    cudaGetSymbolAddress((void**)&p_h1b, g_h1b);
    cudaGetSymbolAddress((void**)&p_wqb, g_wqb);
    cudaGetSymbolAddress((void**)&p_wkvb,g_wkvb);
    cudaGetSymbolAddress((void**)&p_wrb, g_wrb);
    cudaGetSymbolAddress((void**)&p_f1b, g_f1b);
    cudaGetSymbolAddress((void**)&p_f2b, g_f2b);
    cudaGetSymbolAddress((void**)&p_bkv, g_bkv);

    cudaFuncSetAttribute(gemm_bf16<1>, cudaFuncAttributeMaxDynamicSharedMemorySize, SMEM_REQ);
    cudaFuncSetAttribute(gemm_bf16<2>, cudaFuncAttributeMaxDynamicSharedMemorySize, SMEM_REQ);
    cudaFuncSetAttribute(gemm_bf16<4>, cudaFuncAttributeMaxDynamicSharedMemorySize, SMEM_REQ);
    cudaFuncSetAttribute(gemm_bf16<6>, cudaFuncAttributeMaxDynamicSharedMemorySize, SMEM_REQ);
    cudaFuncSetAttribute(ln_x_kernel, cudaFuncAttributeMaxDynamicSharedMemorySize, LNX_SMEM);

    // 0) fused prep: all weight conversions + bias concat + FULL ctx zero
    prep_kernel<<<(PREP_UNITS + 255)/256, 256>>>(wq, wk, wv, wr, fc1_w, fc2_w, bk, bv,
                                                 p_wqb, p_wkvb, p_wrb, p_f1b, p_f2b,
                                                 p_bkv, p_ctx);

    // 1) LN1(x) fused with transpose (-> xnb bf16 + xnT f32); LN(v) plain
    ln_x_kernel<<<Mrows / 32, 1024, LNX_SMEM>>>(x, ln1_w, ln1_b, p_xnb, p_xnT);
    ln_kernel<<<Mrows, 256>>>(v, lnv_w, lnv_b, p_vnb);

    // 2) projections: q (N=512, bf16 out), fused k|v (N=1024, bf16 out)
    gemm_bf16<4><<<dim3(Cn / 128, Mrows / 128), 256, SMEM_REQ>>>(
        p_xnb, p_wqb, bq, nullptr, nullptr, p_qb, Mrows, Cn, Cn);
    gemm_bf16<4><<<dim3(CKV / 128, Mrows / 128), 256, SMEM_REQ>>>(
        p_vnb, p_wkvb, p_bkv, nullptr, nullptr, p_kvb, Mrows, CKV, Cn);

    // 3) k softmax stats (single pass, coalesced); exp applied inline in context
    k_stats<<<dim3(Cn / 64, Bn), 256>>>(p_kvb, p_kmax, p_kinv);

    // 4) context = softmax_l(k)^T @ val
    context_kernel<<<dim3(16, Hn, Bn), 256>>>(p_kvb, p_kmax, p_kinv, p_ctx);

    // 5) aggT = (ctx^T @ softmax(q))^T  -> (B, L, C) bf16
    agg_kernel<<<dim3(Ln / 128, Hn, Bn), 256>>>(p_qb, p_ctx, p_aggT);

    // 6) reproj fused: x1 = wr·aggT + br + xnT + x   (writes x1 directly)
    gemm_bf16<6><<<dim3(Ln / 128, Cn / 128, Bn), 256, SMEM_REQ>>>(
        p_wrb, p_aggT, br, p_xnT, x, p_x1, Cn, Ln, Cn);

    // 7) x1n = LN(x1) (bf16)
    ln_kernel<<<Mrows, 256>>>(p_x1, ln2_w, ln2_b, p_x1nb);

    // 8) MLP
    gemm_bf16<1><<<dim3(HID / 128, Mrows / 128), 256, SMEM_REQ>>>(
        p_x1nb, p_f1b, fc1_b, nullptr, nullptr, p_h1b, Mrows, HID, Cn);
    gemm_bf16<2><<<dim3(Cn / 128, Mrows / 128), 256, SMEM_REQ>>>(
        p_h1b, p_f2b, fc2_b, p_x1, nullptr, out, Mrows, Cn, HID);
}

// round 13
// speedup vs baseline: 1.0275x; 1.0043x over previous
#include <cuda_runtime.h>
#include <cuda_bf16.h>
#include <math.h>
#include <stdint.h>

#define Bn   8
#define Ln   9216
#define Cn   512
#define Hn   8
#define DK   64
#define HID  2048
#define Mrows (Bn*Ln)          // 73728
#define QKV  1536              // fused q|k|v width
#define CTXN (Bn*Hn*DK*DK)     // 262144 floats

// ---------------- scratch (device globals: no runtime allocation) ----------
__device__ float          g_xnT [Mrows*Cn];   // fp32 xn transposed (B,C,L)
__device__ __nv_bfloat16  g_xnb [Mrows*Cn];   // bf16 xn (GEMM A)
__device__ __nv_bfloat16  g_vnb [Mrows*Cn];   // bf16 vn (GEMM A)
__device__ __nv_bfloat16  g_qkvb[Mrows*QKV];  // bf16 fused [q | k | v]
__device__ float          g_kinv[Bn*Cn];
__device__ float          g_ctx [CTXN];
__device__ __nv_bfloat16  g_aggT[Mrows*Cn];   // (B, L, C) bf16 (reproj B operand)
__device__ float          g_x1  [Mrows*Cn];   // x1 = reproj + br + xn^T + x (flat)
__device__ __nv_bfloat16  g_x1nb[Mrows*Cn];   // bf16 LN2 out (fc1 A)
__device__ __nv_bfloat16  g_h1b [Mrows*HID];  // bf16 gelu(fc1) (fc2 A)
// bf16 weights
__device__ __nv_bfloat16  g_wqkvb[QKV*Cn];    // [wq ; wk ; wv]
__device__ __nv_bfloat16  g_wrb  [Cn*Cn];
__device__ __nv_bfloat16  g_f1b  [HID*Cn];
__device__ __nv_bfloat16  g_f2b  [Cn*HID];
__device__ float          g_bqkv [QKV];       // [bq ; bk ; bv]

// ---------------- asm helpers ------------------------------------------------
__device__ __forceinline__ uint32_t smem_u32(const void* p) {
    uint32_t a;
    asm("{ .reg .u64 t; cvta.to.shared.u64 t, %1; cvt.u32.u64 %0, t; }" : "=r"(a) : "l"(p));
    return a;
}
__device__ __forceinline__ void ldsm4(uint32_t* r, uint32_t a) {
    asm volatile("ldmatrix.sync.aligned.m8n8.x4.shared.b16 {%0,%1,%2,%3}, [%4];"
        : "=r"(r[0]), "=r"(r[1]), "=r"(r[2]), "=r"(r[3]) : "r"(a));
}
__device__ __forceinline__ void mma_bf16(float* c, const uint32_t* a, const uint32_t* b) {
    asm volatile("mma.sync.aligned.m16n8k16.row.col.f32.bf16.bf16.f32 "
        "{%0,%1,%2,%3}, {%4,%5,%6,%7}, {%8,%9}, {%0,%1,%2,%3};"
        : "+f"(c[0]), "+f"(c[1]), "+f"(c[2]), "+f"(c[3])
        : "r"(a[0]), "r"(a[1]), "r"(a[2]), "r"(a[3]), "r"(b[0]), "r"(b[1]));
}
__device__ __forceinline__ void cp16(uint32_t dst, const void* src) {
    asm volatile("cp.async.cg.shared.global [%0], [%1], 16;" :: "r"(dst), "l"(src));
}
#define CP_COMMIT() asm volatile("cp.async.commit_group;" ::: "memory")
#define CP_WAIT2()  asm volatile("cp.async.wait_group 2;" ::: "memory")

// smem tile geometry: rows of 32 bf16 (64B) padded to 80B -> conflict-free LDSM
#define ROWB   80
#define STG_A  (128*ROWB)          // 10240
#define STG    (2*STG_A)           // 20480 per stage
#define NST    4
#define SMEM_REQ (NST*STG)         // 81920  (2 CTAs/SM)

// ---------------- misc device helpers ---------------------------------------
__device__ __forceinline__ float gelu_exact(float x) {
    return 0.5f * x * (1.0f + erff(x * 0.70710678118654752f));
}

// fast exp in the FMA pipe (no MUFU): exp(x) = 2^(x*log2e)
// magic-number round-to-nearest + degree-5 Taylor for 2^r on [-0.5, 0.5].
// rel err ~2.4e-6. Valid for x in [-60, 60].
__device__ __forceinline__ float fexp(float x) {
    x = fmaxf(x, -60.0f);
    float y = x * 1.4426950408889634f;
    float t = y + 12582912.0f;            // 1.5 * 2^23
    float n = t - 12582912.0f;            // round(y)
    float r = y - n;                      // [-0.5, 0.5]
    float p = fmaf(0.0013333558f, r, 0.0096181298f);
    p = fmaf(p, r, 0.0555041087f);
    p = fmaf(p, r, 0.2402265070f);
    p = fmaf(p, r, 0.6931471806f);
    p = fmaf(p, r, 1.0f);
    int ni = (int)n;
    return p * __int_as_float((ni + 127) << 23);
}

__device__ __forceinline__ float blockReduceSum256(float v, float* s8, int tid) {
    #pragma unroll
    for (int o = 16; o > 0; o >>= 1) v += __shfl_xor_sync(0xffffffffu, v, o);
    int lane = tid & 31, w = tid >> 5;
    if (lane == 0) s8[w] = v;
    __syncthreads();
    if (w == 0) {
        v = (lane < 8) ? s8[lane] : 0.f;
        #pragma unroll
        for (int o = 4; o > 0; o >>= 1) v += __shfl_xor_sync(0xffffffffu, v, o);
        if (lane == 0) s8[0] = v;
    }
    __syncthreads();
    float r = s8[0];
    __syncthreads();
    return r;
}

// ---------------- bf16 GEMM (NT): C[M,N] = A[M,K]·W[N,K]^T + epilogue -------
// CTA 128x128, warp tile 64x32 (8 warps), K-chunk 32, 4-stage cp.async,
// single __syncthreads per chunk (prefetch kt+3 after the barrier).
// EPI: 1 bias(n)+gelu -> bf16    2 bias(n)+res -> f32
//      6 reproj fused: bias(m) + res(xnT flat) + res2(x flat), out f32
//        stride Ln, batch z  (writes x1 directly)
//      7 qkv: bias(n) -> bf16; A = (n0 < Cn) ? A : (bf16*)res
template<int EPI>
__global__ __launch_bounds__(256)
void gemm_bf16(const __nv_bfloat16* __restrict__ A, const __nv_bfloat16* __restrict__ W,
               const float* __restrict__ bias, const float* __restrict__ res,
               const float* __restrict__ res2,
               void* __restrict__ Cout, int Msz, int Nsz, int Ksz) {
    extern __shared__ char smem[];
    uint32_t sbase = smem_u32(smem);

    int tid = threadIdx.x;
    int wid = tid >> 5, lane = tid & 31;
    int m0 = blockIdx.y * 128, n0 = blockIdx.x * 128;
    int wm = (wid & 1) * 64, wn = (wid >> 1) * 32;
    int lrow = lane & 15;
    int lko  = (lane >> 4) * 16;

    const __nv_bfloat16* Aop = A;
    const __nv_bfloat16* Wop = W;
    const float* respZ = res;
    const float* res2Z = res2;
    float* CpF = (float*)Cout;
    __nv_bfloat16* CpH = (__nv_bfloat16*)Cout;
    if (EPI == 7) {
        if (n0 >= Cn) Aop = (const __nv_bfloat16*)res;   // k|v columns use vn
    }
    if (EPI == 6) {
        size_t z = blockIdx.z;
        size_t zoff = z * (size_t)Cn * Ln;
        Wop   = W + z * (size_t)Ln * Cn;    // aggT batch slice [L, C] bf16
        respZ = res + zoff;                 // xnT (B,C,L) flat slice
        res2Z = res2 + zoff;                // x (flat-aligned) slice
        CpF   = (float*)Cout + zoff;
    }

    float acc[4][4][4];
    #pragma unroll
    for (int i = 0; i < 4; i++)
        #pragma unroll
        for (int j = 0; j < 4; j++)
            #pragma unroll
            for (int c = 0; c < 4; c++) acc[i][j][c] = 0.f;

    int arow = tid >> 2;          // 0..63
    int acol = tid & 3;           // 0..3 (16B chunks of 8 bf16)

    auto load_chunk = [&](int kt, int s) {
        uint32_t dA = sbase + s * STG;
        uint32_t dB = dA + STG_A;
        const __nv_bfloat16* ga = Aop + (size_t)(m0 + arow) * Ksz + kt * 32 + acol * 8;
        cp16(dA + (uint32_t)(arow * ROWB + acol * 16), ga);
        cp16(dA + (uint32_t)((arow + 64) * ROWB + acol * 16), ga + (size_t)64 * Ksz);
        const __nv_bfloat16* gb = Wop + (size_t)(n0 + arow) * Ksz + kt * 32 + acol * 8;
        cp16(dB + (uint32_t)(arow * ROWB + acol * 16), gb);
        cp16(dB + (uint32_t)((arow + 64) * ROWB + acol * 16), gb + (size_t)64 * Ksz);
        CP_COMMIT();
    };

    int nk = Ksz >> 5;
    load_chunk(0, 0);
    load_chunk(1, 1);
    load_chunk(2, 2);

    for (int kt = 0; kt < nk; kt++) {
        int s = kt & 3;
        CP_WAIT2();
        __syncthreads();
        // prefetch into slot (kt+3)&3, freed by the compute of iteration kt-1
        if (kt + 3 < nk) load_chunk(kt + 3, (kt + 3) & 3);
        else CP_COMMIT();           // keep group count uniform for wait_group

        uint32_t sA = sbase + s * STG;
        uint32_t sB = sA + STG_A;
        #pragma unroll
        for (int ks = 0; ks < 2; ks++) {
            uint32_t af[4][4], bf[2][4];
            #pragma unroll
            for (int mt = 0; mt < 4; mt++)
                ldsm4(af[mt], sA + (uint32_t)((wm + mt*16 + lrow) * ROWB + ks*32 + lko));
            #pragma unroll
            for (int g = 0; g < 2; g++)
                ldsm4(bf[g], sB + (uint32_t)((wn + g*16 + lrow) * ROWB + ks*32 + lko));
            #pragma unroll
            for (int mt = 0; mt < 4; mt++)
                #pragma unroll
                for (int nt = 0; nt < 4; nt++) {
                    uint32_t bb[2] = { bf[nt>>1][nt&1], bf[nt>>1][(nt&1) + 2] };
                    mma_bf16(acc[mt][nt], af[mt], bb);
                }
        }
    }

    // -------- epilogue (direct STG from accumulators)
    int rm = lane >> 2, cn = (lane & 3) * 2;
    #pragma unroll
    for (int mt = 0; mt < 4; mt++) {
        int m = m0 + wm + mt*16 + rm;
        float bm0 = 0.f, bm1 = 0.f;
        if (EPI == 6) { bm0 = bias[m]; bm1 = bias[m + 8]; }
        #pragma unroll
        for (int nt = 0; nt < 4; nt++) {
            int n = n0 + wn + nt*8 + cn;
            float* c = acc[mt][nt];
            if (EPI == 1) {
                float2 bb = *(const float2*)&bias[n];
                __nv_bfloat162 p0 = __floats2bfloat162_rn(gelu_exact(c[0]+bb.x), gelu_exact(c[1]+bb.y));
                __nv_bfloat162 p1 = __floats2bfloat162_rn(gelu_exact(c[2]+bb.x), gelu_exact(c[3]+bb.y));
                *(__nv_bfloat162*)&CpH[(size_t)m * Nsz + n]     = p0;
                *(__nv_bfloat162*)&CpH[(size_t)(m+8) * Nsz + n] = p1;
            } else if (EPI == 2) {
                float2 bb = *(const float2*)&bias[n];
                float2 r0 = *(const float2*)&respZ[(size_t)m * Nsz + n];
                float2 r1 = *(const float2*)&respZ[(size_t)(m+8) * Nsz + n];
                *(float2*)&CpF[(size_t)m * Nsz + n]     = make_float2(c[0]+bb.x+r0.x, c[1]+bb.y+r0.y);
                *(float2*)&CpF[(size_t)(m+8) * Nsz + n] = make_float2(c[2]+bb.x+r1.x, c[3]+bb.y+r1.y);
            } else if (EPI == 7) {
                float2 bb = *(const float2*)&bias[n];
                __nv_bfloat162 p0 = __floats2bfloat162_rn(c[0]+bb.x, c[1]+bb.y);
                __nv_bfloat162 p1 = __floats2bfloat162_rn(c[2]+bb.x, c[3]+bb.y);
                *(__nv_bfloat162*)&CpH[(size_t)m * Nsz + n]     = p0;
                *(__nv_bfloat162*)&CpH[(size_t)(m+8) * Nsz + n] = p1;
            } else {  // EPI == 6: bias(m) + xnT_flat + x_flat, write x1
                size_t f0 = (size_t)m * Ln + n;
                size_t f1 = (size_t)(m+8) * Ln + n;
                float2 t0 = *(const float2*)&respZ[f0];
                float2 t1 = *(const float2*)&respZ[f1];
                float2 u0 = *(const float2*)&res2Z[f0];
                float2 u1 = *(const float2*)&res2Z[f1];
                *(float2*)&CpF[f0] = make_float2(c[0]+bm0+t0.x+u0.x, c[1]+bm0+t0.y+u0.y);
                *(float2*)&CpF[f1] = make_float2(c[2]+bm1+t1.x+u1.x, c[3]+bm1+t1.y+u1.y);
            }
        }
    }
}

// ---------------- fused prep: all weight cvt + bias concat + ctx zero --------
// unit = 4 elements. Regions (in 4-elem units):
//   [0, 65536)          wq   -> wqkvb[0:]
//   [65536, 131072)     wk   -> wqkvb[Cn*Cn:]
//   [131072, 196608)    wv   -> wqkvb[2*Cn*Cn:]
//   [196608, 262144)    wr   -> wrb
//   [262144, 524288)    fc1  -> f1b
//   [524288, 786432)    fc2  -> f2b
//   [786432, 786816)    bq|bk|bv -> bqkv (1536 f32 = 384 units)
//   [786816, 852352)    ctx zero (CTXN = 262144 floats = 65536 units)
#define PREP_UNITS 852352
__global__ void prep_kernel(const float* __restrict__ wq, const float* __restrict__ wk,
                            const float* __restrict__ wv, const float* __restrict__ wr,
                            const float* __restrict__ f1, const float* __restrict__ f2,
                            const float* __restrict__ bq, const float* __restrict__ bk,
                            const float* __restrict__ bv,
                            __nv_bfloat16* __restrict__ wqkvb,
                            __nv_bfloat16* __restrict__ wrb, __nv_bfloat16* __restrict__ f1b,
                            __nv_bfloat16* __restrict__ f2b, float* __restrict__ bqkv,
                            float* __restrict__ ctx) {
    int u = blockIdx.x * blockDim.x + threadIdx.x;
    const float* src;
    __nv_bfloat16* dst;
    int off;
    if (u < 65536)        { src = wq; dst = wqkvb; off = u; }
    else if (u < 131072)  { src = wk; dst = wqkvb + (size_t)Cn*Cn;   off = u - 65536; }
    else if (u < 196608)  { src = wv; dst = wqkvb + (size_t)2*Cn*Cn; off = u - 131072; }
    else if (u < 262144)  { src = wr; dst = wrb;  off = u - 196608; }
    else if (u < 524288)  { src = f1; dst = f1b;  off = u - 262144; }
    else if (u < 786432)  { src = f2; dst = f2b;  off = u - 524288; }
    else if (u < 786816)  {
        int i = (u - 786432) * 4;
        #pragma unroll
        for (int j = 0; j < 4; j++) {
            int k = i + j;
            bqkv[k] = (k < Cn) ? bq[k] : (k < 2*Cn ? bk[k - Cn] : bv[k - 2*Cn]);
        }
        return;
    } else if (u < 852352) {
        int i = (u - 786816) * 4;
        *(float4*)&ctx[i] = make_float4(0.f, 0.f, 0.f, 0.f);
        return;
    } else return;
    int i = off * 4;
    float4 v = *(const float4*)(src + i);
    *(__nv_bfloat162*)(dst + i)     = __floats2bfloat162_rn(v.x, v.y);
    *(__nv_bfloat162*)(dst + i + 2) = __floats2bfloat162_rn(v.z, v.w);
}

// ------- fused LN1(x) + transpose: writes xnb (bf16, (B,L,C)) + xnT (f32, (B,C,L))
#define LNX_PITCH 513
#define LNX_SMEM  (32 * LNX_PITCH * 4)   // 65,664 B
__global__ __launch_bounds__(1024)
void ln_x_kernel(const float* __restrict__ in, const float* __restrict__ w,
                 const float* __restrict__ b, __nv_bfloat16* __restrict__ outb,
                 float* __restrict__ outT) {
    extern __shared__ float s[];
    int tid = threadIdx.x;
    int wrp = tid >> 5, lane = tid & 31;
    int row0 = blockIdx.x * 32;
    int row = row0 + wrp;
    size_t base = (size_t)row * Cn;

    float4 v[4];
    float sum = 0.f;
    #pragma unroll
    for (int j = 0; j < 4; j++) {
        v[j] = *(const float4*)(in + base + lane * 4 + j * 128);
        sum += v[j].x + v[j].y + v[j].z + v[j].w;
    }
    #pragma unroll
    for (int o = 16; o > 0; o >>= 1) sum += __shfl_xor_sync(0xffffffffu, sum, o);
    float mean = sum * (1.0f / Cn);
    float vs = 0.f;
    #pragma unroll
    for (int j = 0; j < 4; j++) {
        float d0 = v[j].x - mean, d1 = v[j].y - mean, d2 = v[j].z - mean, d3 = v[j].w - mean;
        vs += d0*d0 + d1*d1 + d2*d2 + d3*d3;
    }
    #pragma unroll
    for (int o = 16; o > 0; o >>= 1) vs += __shfl_xor_sync(0xffffffffu, vs, o);
    float rs = rsqrtf(vs * (1.0f / Cn) + 1e-5f);

    float* srow = s + wrp * LNX_PITCH;
    #pragma unroll
    for (int j = 0; j < 4; j++) {
        int c = lane * 4 + j * 128;
        float4 ww = *(const float4*)(w + c);
        float4 bb = *(const float4*)(b + c);
        float o0 = (v[j].x - mean) * rs * ww.x + bb.x;
        float o1 = (v[j].y - mean) * rs * ww.y + bb.y;
        float o2 = (v[j].z - mean) * rs * ww.z + bb.z;
        float o3 = (v[j].w - mean) * rs * ww.w + bb.w;
        *(__nv_bfloat162*)(outb + base + c)     = __floats2bfloat162_rn(o0, o1);
        *(__nv_bfloat162*)(outb + base + c + 2) = __floats2bfloat162_rn(o2, o3);
        srow[c] = o0; srow[c+1] = o1; srow[c+2] = o2; srow[c+3] = o3;
    }
    __syncthreads();

    int bz = row0 / Ln;
    int lb = row0 - bz * Ln;
    float* op = outT + (size_t)bz * Cn * Ln + lb;
    #pragma unroll
    for (int it = 0; it < 4; it++) {
        int idx = it * 1024 + tid;
        int c = idx >> 3, p = idx & 7;
        int l = p * 4;
        float4 ov = make_float4(s[(l+0) * LNX_PITCH + c], s[(l+1) * LNX_PITCH + c],
                                s[(l+2) * LNX_PITCH + c], s[(l+3) * LNX_PITCH + c]);
        *(float4*)(op + (size_t)c * Ln + l) = ov;
    }
}

// ---------------- LayerNorm (plain, bf16 out) --------------------------------
__global__ void ln_kernel(const float* __restrict__ in, const float* __restrict__ w,
                          const float* __restrict__ b, __nv_bfloat16* __restrict__ outb) {
    __shared__ float s8[8];
    int row = blockIdx.x, t = threadIdx.x;
    size_t base = (size_t)row * Cn;
    float v0 = in[base + t], v1 = in[base + t + 256];
    float mean = blockReduceSum256(v0 + v1, s8, t) * (1.0f / Cn);
    float d0 = v0 - mean, d1 = v1 - mean;
    float var = blockReduceSum256(d0*d0 + d1*d1, s8, t) * (1.0f / Cn);
    float rs = rsqrtf(var + 1e-5f);
    outb[base + t]       = __float2bfloat16_rn(d0 * rs * w[t]       + b[t]);
    outb[base + t + 256] = __float2bfloat16_rn(d1 * rs * w[t + 256] + b[t + 256]);
}

// ---------------- k stats: per (b, ck) sum of exp over L (no max shift) ------
// 64 contiguous channels per block -> 128B coalesced rows. Poly exp (FMA pipe).
__global__ void k_stats(const __nv_bfloat16* __restrict__ qkvb,
                        float* __restrict__ kinv) {
    __shared__ float ss[4][64];
    int tid = threadIdx.x;
    int c = tid & 63, w4 = tid >> 6;      // 0..3
    int ck = blockIdx.x * 64 + c;
    int b  = blockIdx.y;
    size_t base = (size_t)b * Ln * QKV + Cn + ck;   // k at offset Cn

    float s = 0.f;
    for (int l = w4; l < Ln; l += 4)
        s += fexp(__bfloat162float(qkvb[base + (size_t)l * QKV]));
    ss[w4][c] = s;
    __syncthreads();
    if (w4 == 0) {
        s = ss[0][c] + ss[1][c] + ss[2][c] + ss[3][c];
        kinv[b * Cn + ck] = 1.0f / s;
    }
}

// ------- context[b,h,k,v] += sum_l exp(k)/Z * val (poly exp, bf16 in) --------
__global__ __launch_bounds__(256)
void context_kernel(const __nv_bfloat16* __restrict__ qkvb,
                    const float* __restrict__ kinv,
                    float* __restrict__ ctx) {
    __shared__ float sK[8][64];
    __shared__ float sV[8][64];
    int b = blockIdx.z, h = blockIdx.y;
    int l0 = blockIdx.x * (Ln / 16);
    int tid = threadIdx.x;
    int tx = tid & 15, ty = tid >> 4;
    int li = tid >> 5, cc = tid & 31;

    float acc[4][4] = {};
    for (int lc = l0; lc < l0 + Ln / 16; lc += 8) {
        size_t idx = ((size_t)(b * Ln + lc + li)) * QKV + Cn + h * DK + cc;  // k
        sK[li][cc]      = fexp(__bfloat162float(qkvb[idx]));
        sK[li][cc + 32] = fexp(__bfloat162float(qkvb[idx + 32]));
        sV[li][cc]      = __bfloat162float(qkvb[idx + Cn]);        // v = k + Cn
        sV[li][cc + 32] = __bfloat162float(qkvb[idx + Cn + 32]);
        __syncthreads();
        #pragma unroll
        for (int l = 0; l < 8; l++) {
            float kvv[4], vv[4];
            #pragma unroll
            for (int i = 0; i < 4; i++) { kvv[i] = sK[l][ty*4+i]; vv[i] = sV[l][tx*4+i]; }
            #pragma unroll
            for (int i = 0; i < 4; i++)
                #pragma unroll
                for (int j = 0; j < 4; j++) acc[i][j] = fmaf(kvv[i], vv[j], acc[i][j]);
        }
        __syncthreads();
    }
    size_t cb = (size_t)(b * Hn + h) * DK * DK;
    #pragma unroll
    for (int i = 0; i < 4; i++) {
        float zi = kinv[b * Cn + h * DK + ty*4 + i];
        #pragma unroll
        for (int j = 0; j < 4; j++)
            atomicAdd(&ctx[cb + (size_t)(ty*4+i) * DK + tx*4+j], acc[i][j] * zi);
    }
}

// ---- aggT[b, l, h*64+v] = sum_k ctx[b,h,k,v] * softmax_k(q[b,l,h,:]) -------
// q softmax without max shift (poly exp); bf16 out.
__global__ __launch_bounds__(256)
void agg_kernel(const __nv_bfloat16* __restrict__ qkvb, const float* __restrict__ ctx,
                __nv_bfloat16* __restrict__ aggT) {
    __shared__ float sC[64][64];
    __shared__ float sQ[128][65];   // padded: conflict-free row access
    int b = blockIdx.z, h = blockIdx.y, l0 = blockIdx.x * 128;
    int tid = threadIdx.x;
    int tx = tid & 15, ty = tid >> 4;

    size_t cb = (size_t)(b * Hn + h) * DK * DK;
    for (int f = tid; f < 4096; f += 256) sC[f >> 6][f & 63] = ctx[cb + f];
    for (int f = tid; f < 8192; f += 256) {
        int l = f >> 6, kk = f & 63;
        sQ[l][kk] = __bfloat162float(qkvb[((size_t)(b * Ln + l0 + l)) * QKV + h * DK + kk]);
    }
    __syncthreads();

    // in-block q softmax over the 64 channels of this head (2 threads/row)
    {
        int r = tid >> 1;
        int off = (tid & 1) * 32;
        float s = 0.f;
        #pragma unroll
        for (int j = 0; j < 32; j++) {
            float e = fexp(sQ[r][off + j]);
            sQ[r][off + j] = e;
            s += e;
        }
        s += __shfl_xor_sync(0xffffffffu, s, 1);
        float inv = 1.0f / s;
        #pragma unroll
        for (int j = 0; j < 32; j++) sQ[r][off + j] *= inv;
    }
    __syncthreads();

    float acc[4][8] = {};
    #pragma unroll
    for (int k = 0; k < 64; k++) {
        float cv[4], qv[8];
        #pragma unroll
        for (int i = 0; i < 4; i++) cv[i] = sC[k][tx*4+i];
        #pragma unroll
        for (int j = 0; j < 8; j++) qv[j] = sQ[ty*8+j][k];
        #pragma unroll
        for (int i = 0; i < 4; i++)
            #pragma unroll
            for (int j = 0; j < 8; j++) acc[i][j] = fmaf(cv[i], qv[j], acc[i][j]);
    }
    #pragma unroll
    for (int j = 0; j < 8; j++) {
        size_t ob = ((size_t)(b * Ln + l0 + ty*8 + j)) * Cn + h * DK + tx*4;
        *(__nv_bfloat162*)&aggT[ob]     = __floats2bfloat162_rn(acc[0][j], acc[1][j]);
        *(__nv_bfloat162*)&aggT[ob + 2] = __floats2bfloat162_rn(acc[2][j], acc[3][j]);
    }
}

// ---------------- host launcher ---------------------------------------------
extern "C" void kernel_launch(void* const* d_in, const int* in_sizes, int n_in,
                              void* d_out, int out_size) {
    (void)in_sizes; (void)n_in; (void)out_size;
    const float* x     = (const float*)d_in[0];
    const float* v     = (const float*)d_in[1];
    const float* ln1_w = (const float*)d_in[4];
    const float* ln1_b = (const float*)d_in[5];
    const float* lnv_w = (const float*)d_in[6];
    const float* lnv_b = (const float*)d_in[7];
    const float* ln2_w = (const float*)d_in[8];
    const float* ln2_b = (const float*)d_in[9];
    const float* wq    = (const float*)d_in[10];
    const float* bq    = (const float*)d_in[11];
    const float* wk    = (const float*)d_in[12];
    const float* bk    = (const float*)d_in[13];
    const float* wv    = (const float*)d_in[14];
    const float* bv    = (const float*)d_in[15];
    const float* wr    = (const float*)d_in[16];
    const float* br    = (const float*)d_in[17];
    const float* fc1_w = (const float*)d_in[18];
    const float* fc1_b = (const float*)d_in[19];
    const float* fc2_w = (const float*)d_in[20];
    const float* fc2_b = (const float*)d_in[21];
    float* out = (float*)d_out;

    float *p_xnT, *p_kinv, *p_ctx, *p_x1, *p_bqkv;
    __nv_bfloat16 *p_xnb, *p_vnb, *p_qkvb, *p_aggT, *p_x1nb, *p_h1b;
    __nv_bfloat16 *p_wqkvb, *p_wrb, *p_f1b, *p_f2b;
    cudaGetSymbolAddress((void**)&p_xnT, g_xnT);
    cudaGetSymbolAddress((void**)&p_xnb, g_xnb);
    cudaGetSymbolAddress((void**)&p_vnb, g_vnb);
    cudaGetSymbolAddress((void**)&p_qkvb,g_qkvb);
    cudaGetSymbolAddress((void**)&p_kinv,g_kinv);
    cudaGetSymbolAddress((void**)&p_ctx, g_ctx);
    cudaGetSymbolAddress((void**)&p_aggT,g_aggT);
    cudaGetSymbolAddress((void**)&p_x1,  g_x1);
    cudaGetSymbolAddress((void**)&p_x1nb,g_x1nb);
    cudaGetSymbolAddress((void**)&p_h1b, g_h1b);
    cudaGetSymbolAddress((void**)&p_wqkvb,g_wqkvb);
    cudaGetSymbolAddress((void**)&p_wrb, g_wrb);
    cudaGetSymbolAddress((void**)&p_f1b, g_f1b);
    cudaGetSymbolAddress((void**)&p_f2b, g_f2b);
    cudaGetSymbolAddress((void**)&p_bqkv,g_bqkv);

    cudaFuncSetAttribute(gemm_bf16<1>, cudaFuncAttributeMaxDynamicSharedMemorySize, SMEM_REQ);
    cudaFuncSetAttribute(gemm_bf16<2>, cudaFuncAttributeMaxDynamicSharedMemorySize, SMEM_REQ);
    cudaFuncSetAttribute(gemm_bf16<6>, cudaFuncAttributeMaxDynamicSharedMemorySize, SMEM_REQ);
    cudaFuncSetAttribute(gemm_bf16<7>, cudaFuncAttributeMaxDynamicSharedMemorySize, SMEM_REQ);
    cudaFuncSetAttribute(ln_x_kernel, cudaFuncAttributeMaxDynamicSharedMemorySize, LNX_SMEM);

    // 0) fused prep: all weight conversions + bias concat + FULL ctx zero
    prep_kernel<<<(PREP_UNITS + 255)/256, 256>>>(wq, wk, wv, wr, fc1_w, fc2_w,
                                                 bq, bk, bv,
                                                 p_wqkvb, p_wrb, p_f1b, p_f2b,
                                                 p_bqkv, p_ctx);

    // 1) LN1(x) fused with transpose (-> xnb bf16 + xnT f32); LN(v) plain
    ln_x_kernel<<<Mrows / 32, 1024, LNX_SMEM>>>(x, ln1_w, ln1_b, p_xnb, p_xnT);
    ln_kernel<<<Mrows, 256>>>(v, lnv_w, lnv_b, p_vnb);

    // 2) fused q|k|v projection (N=1536; A chosen per n-block)
    gemm_bf16<7><<<dim3(QKV / 128, Mrows / 128), 256, SMEM_REQ>>>(
        p_xnb, p_wqkvb, p_bqkv, (const float*)p_vnb, nullptr, p_qkvb, Mrows, QKV, Cn);

    // 3) k softmax denominators (single pass, poly exp, no max shift)
    k_stats<<<dim3(Cn / 64, Bn), 256>>>(p_qkvb, p_kinv);

    // 4) context = softmax_l(k)^T @ val
    context_kernel<<<dim3(16, Hn, Bn), 256>>>(p_qkvb, p_kinv, p_ctx);

    // 5) aggT = (ctx^T @ softmax(q))^T  -> (B, L, C) bf16
    agg_kernel<<<dim3(Ln / 128, Hn, Bn), 256>>>(p_qkvb, p_ctx, p_aggT);

    // 6) reproj fused: x1 = wr·aggT + br + xnT + x   (writes x1 directly)
    gemm_bf16<6><<<dim3(Ln / 128, Cn / 128, Bn), 256, SMEM_REQ>>>(
        p_wrb, p_aggT, br, p_xnT, x, p_x1, Cn, Ln, Cn);

    // 7) x1n = LN(x1) (bf16)
    ln_kernel<<<Mrows, 256>>>(p_x1, ln2_w, ln2_b, p_x1nb);

    // 8) MLP
    gemm_bf16<1><<<dim3(HID / 128, Mrows / 128), 256, SMEM_REQ>>>(
        p_x1nb, p_f1b, fc1_b, nullptr, nullptr, p_h1b, Mrows, HID, Cn);
    gemm_bf16<2><<<dim3(Cn / 128, Mrows / 128), 256, SMEM_REQ>>>(
        p_h1b, p_f2b, fc2_b, p_x1, nullptr, out, Mrows, Cn, HID);
}

// round 14
// speedup vs baseline: 1.1544x; 1.1235x over previous
#include <cuda_runtime.h>
#include <cuda_bf16.h>
#include <math.h>
#include <stdint.h>

#define Bn   8
#define Ln   9216
#define Cn   512
#define Hn   8
#define DK   64
#define HID  2048
#define Mrows (Bn*Ln)          // 73728
#define QKV  1536              // fused q|k|v width
#define CTXN (Bn*Hn*DK*DK)     // 262144 floats

// ---------------- scratch (device globals: no runtime allocation) ----------
__device__ float          g_xnT [Mrows*Cn];   // fp32 xn transposed (B,C,L)
__device__ __nv_bfloat16  g_xnb [Mrows*Cn];   // bf16 xn (GEMM A)
__device__ __nv_bfloat16  g_vnb [Mrows*Cn];   // bf16 vn (GEMM A)
__device__ __nv_bfloat16  g_qkvb[Mrows*QKV];  // bf16 fused [q | k | v]
__device__ float          g_ksum[Bn*Cn];      // per-(b,ck) sum of exp(k) over L
__device__ float          g_ctx [CTXN];       // UNNORMALIZED context
__device__ __nv_bfloat16  g_aggT[Mrows*Cn];   // (B, L, C) bf16 (reproj B operand)
__device__ float          g_x1  [Mrows*Cn];   // x1 = reproj + br + xn^T + x (flat)
__device__ __nv_bfloat16  g_x1nb[Mrows*Cn];   // bf16 LN2 out (fc1 A)
__device__ __nv_bfloat16  g_h1b [Mrows*HID];  // bf16 gelu(fc1) (fc2 A)
// bf16 weights
__device__ __nv_bfloat16  g_wqkvb[QKV*Cn];    // [wq ; wk ; wv]
__device__ __nv_bfloat16  g_wrb  [Cn*Cn];
__device__ __nv_bfloat16  g_f1b  [HID*Cn];
__device__ __nv_bfloat16  g_f2b  [Cn*HID];
__device__ float          g_bqkv [QKV];       // [bq ; bk ; bv]

// ---------------- asm helpers ------------------------------------------------
__device__ __forceinline__ uint32_t smem_u32(const void* p) {
    uint32_t a;
    asm("{ .reg .u64 t; cvta.to.shared.u64 t, %1; cvt.u32.u64 %0, t; }" : "=r"(a) : "l"(p));
    return a;
}
__device__ __forceinline__ void ldsm4(uint32_t* r, uint32_t a) {
    asm volatile("ldmatrix.sync.aligned.m8n8.x4.shared.b16 {%0,%1,%2,%3}, [%4];"
        : "=r"(r[0]), "=r"(r[1]), "=r"(r[2]), "=r"(r[3]) : "r"(a));
}
__device__ __forceinline__ void mma_bf16(float* c, const uint32_t* a, const uint32_t* b) {
    asm volatile("mma.sync.aligned.m16n8k16.row.col.f32.bf16.bf16.f32 "
        "{%0,%1,%2,%3}, {%4,%5,%6,%7}, {%8,%9}, {%0,%1,%2,%3};"
        : "+f"(c[0]), "+f"(c[1]), "+f"(c[2]), "+f"(c[3])
        : "r"(a[0]), "r"(a[1]), "r"(a[2]), "r"(a[3]), "r"(b[0]), "r"(b[1]));
}
__device__ __forceinline__ void cp16(uint32_t dst, const void* src) {
    asm volatile("cp.async.cg.shared.global [%0], [%1], 16;" :: "r"(dst), "l"(src));
}
#define CP_COMMIT() asm volatile("cp.async.commit_group;" ::: "memory")
#define CP_WAIT2()  asm volatile("cp.async.wait_group 2;" ::: "memory")

// smem tile geometry: rows of 32 bf16 (64B) padded to 80B -> conflict-free LDSM
#define ROWB   80
#define STG_A  (128*ROWB)          // 10240
#define STG    (2*STG_A)           // 20480 per stage
#define NST    4
#define SMEM_REQ (NST*STG)         // 81920  (2 CTAs/SM)

// ---------------- misc device helpers ---------------------------------------
__device__ __forceinline__ float gelu_exact(float x) {
    return 0.5f * x * (1.0f + erff(x * 0.70710678118654752f));
}

// fast exp in the FMA pipe (no MUFU): exp(x) = 2^(x*log2e)
// magic-number round-to-nearest + degree-5 poly for 2^r on [-0.5, 0.5].
// rel err ~2.4e-6. Valid for x in [-60, 60].
__device__ __forceinline__ float fexp(float x) {
    x = fmaxf(x, -60.0f);
    float y = x * 1.4426950408889634f;
    float t = y + 12582912.0f;            // 1.5 * 2^23
    float n = t - 12582912.0f;            // round(y)
    float r = y - n;                      // [-0.5, 0.5]
    float p = fmaf(0.0013333558f, r, 0.0096181298f);
    p = fmaf(p, r, 0.0555041087f);
    p = fmaf(p, r, 0.2402265070f);
    p = fmaf(p, r, 0.6931471806f);
    p = fmaf(p, r, 1.0f);
    int ni = (int)n;
    return p * __int_as_float((ni + 127) << 23);
}

__device__ __forceinline__ float blockReduceSum256(float v, float* s8, int tid) {
    #pragma unroll
    for (int o = 16; o > 0; o >>= 1) v += __shfl_xor_sync(0xffffffffu, v, o);
    int lane = tid & 31, w = tid >> 5;
    if (lane == 0) s8[w] = v;
    __syncthreads();
    if (w == 0) {
        v = (lane < 8) ? s8[lane] : 0.f;
        #pragma unroll
        for (int o = 4; o > 0; o >>= 1) v += __shfl_xor_sync(0xffffffffu, v, o);
        if (lane == 0) s8[0] = v;
    }
    __syncthreads();
    float r = s8[0];
    __syncthreads();
    return r;
}

// ---------------- bf16 GEMM (NT): C[M,N] = A[M,K]·W[N,K]^T + epilogue -------
// CTA 128x128, warp tile 64x32 (8 warps), K-chunk 32, 4-stage cp.async,
// single __syncthreads per chunk (prefetch kt+3 after the barrier).
// EPI: 1 bias(n)+gelu -> bf16    2 bias(n)+res -> f32
//      6 reproj fused: bias(m) + res(xnT flat) + res2(x flat), out f32
//        stride Ln, batch z  (writes x1 directly)
//      7 qkv: bias(n) -> bf16; A = (n0 < Cn) ? A : (bf16*)res
template<int EPI>
__global__ __launch_bounds__(256)
void gemm_bf16(const __nv_bfloat16* __restrict__ A, const __nv_bfloat16* __restrict__ W,
               const float* __restrict__ bias, const float* __restrict__ res,
               const float* __restrict__ res2,
               void* __restrict__ Cout, int Msz, int Nsz, int Ksz) {
    extern __shared__ char smem[];
    uint32_t sbase = smem_u32(smem);

    int tid = threadIdx.x;
    int wid = tid >> 5, lane = tid & 31;
    int m0 = blockIdx.y * 128, n0 = blockIdx.x * 128;
    int wm = (wid & 1) * 64, wn = (wid >> 1) * 32;
    int lrow = lane & 15;
    int lko  = (lane >> 4) * 16;

    const __nv_bfloat16* Aop = A;
    const __nv_bfloat16* Wop = W;
    const float* respZ = res;
    const float* res2Z = res2;
    float* CpF = (float*)Cout;
    __nv_bfloat16* CpH = (__nv_bfloat16*)Cout;
    if (EPI == 7) {
        if (n0 >= Cn) Aop = (const __nv_bfloat16*)res;   // k|v columns use vn
    }
    if (EPI == 6) {
        size_t z = blockIdx.z;
        size_t zoff = z * (size_t)Cn * Ln;
        Wop   = W + z * (size_t)Ln * Cn;    // aggT batch slice [L, C] bf16
        respZ = res + zoff;                 // xnT (B,C,L) flat slice
        res2Z = res2 + zoff;                // x (flat-aligned) slice
        CpF   = (float*)Cout + zoff;
    }

    float acc[4][4][4];
    #pragma unroll
    for (int i = 0; i < 4; i++)
        #pragma unroll
        for (int j = 0; j < 4; j++)
            #pragma unroll
            for (int c = 0; c < 4; c++) acc[i][j][c] = 0.f;

    int arow = tid >> 2;          // 0..63
    int acol = tid & 3;           // 0..3 (16B chunks of 8 bf16)

    auto load_chunk = [&](int kt, int s) {
        uint32_t dA = sbase + s * STG;
        uint32_t dB = dA + STG_A;
        const __nv_bfloat16* ga = Aop + (size_t)(m0 + arow) * Ksz + kt * 32 + acol * 8;
        cp16(dA + (uint32_t)(arow * ROWB + acol * 16), ga);
        cp16(dA + (uint32_t)((arow + 64) * ROWB + acol * 16), ga + (size_t)64 * Ksz);
        const __nv_bfloat16* gb = Wop + (size_t)(n0 + arow) * Ksz + kt * 32 + acol * 8;
        cp16(dB + (uint32_t)(arow * ROWB + acol * 16), gb);
        cp16(dB + (uint32_t)((arow + 64) * ROWB + acol * 16), gb + (size_t)64 * Ksz);
        CP_COMMIT();
    };

    int nk = Ksz >> 5;
    load_chunk(0, 0);
    load_chunk(1, 1);
    load_chunk(2, 2);

    for (int kt = 0; kt < nk; kt++) {
        int s = kt & 3;
        CP_WAIT2();
        __syncthreads();
        // prefetch into slot (kt+3)&3, freed by the compute of iteration kt-1
        if (kt + 3 < nk) load_chunk(kt + 3, (kt + 3) & 3);
        else CP_COMMIT();           // keep group count uniform for wait_group

        uint32_t sA = sbase + s * STG;
        uint32_t sB = sA + STG_A;
        #pragma unroll
        for (int ks = 0; ks < 2; ks++) {
            uint32_t af[4][4], bf[2][4];
            #pragma unroll
            for (int mt = 0; mt < 4; mt++)
                ldsm4(af[mt], sA + (uint32_t)((wm + mt*16 + lrow) * ROWB + ks*32 + lko));
            #pragma unroll
            for (int g = 0; g < 2; g++)
                ldsm4(bf[g], sB + (uint32_t)((wn + g*16 + lrow) * ROWB + ks*32 + lko));
            #pragma unroll
            for (int mt = 0; mt < 4; mt++)
                #pragma unroll
                for (int nt = 0; nt < 4; nt++) {
                    uint32_t bb[2] = { bf[nt>>1][nt&1], bf[nt>>1][(nt&1) + 2] };
                    mma_bf16(acc[mt][nt], af[mt], bb);
                }
        }
    }

    // -------- epilogue (direct STG from accumulators)
    int rm = lane >> 2, cn = (lane & 3) * 2;
    #pragma unroll
    for (int mt = 0; mt < 4; mt++) {
        int m = m0 + wm + mt*16 + rm;
        float bm0 = 0.f, bm1 = 0.f;
        if (EPI == 6) { bm0 = bias[m]; bm1 = bias[m + 8]; }
        #pragma unroll
        for (int nt = 0; nt < 4; nt++) {
            int n = n0 + wn + nt*8 + cn;
            float* c = acc[mt][nt];
            if (EPI == 1) {
                float2 bb = *(const float2*)&bias[n];
                __nv_bfloat162 p0 = __floats2bfloat162_rn(gelu_exact(c[0]+bb.x), gelu_exact(c[1]+bb.y));
                __nv_bfloat162 p1 = __floats2bfloat162_rn(gelu_exact(c[2]+bb.x), gelu_exact(c[3]+bb.y));
                *(__nv_bfloat162*)&CpH[(size_t)m * Nsz + n]     = p0;
                *(__nv_bfloat162*)&CpH[(size_t)(m+8) * Nsz + n] = p1;
            } else if (EPI == 2) {
                float2 bb = *(const float2*)&bias[n];
                float2 r0 = *(const float2*)&respZ[(size_t)m * Nsz + n];
                float2 r1 = *(const float2*)&respZ[(size_t)(m+8) * Nsz + n];
                *(float2*)&CpF[(size_t)m * Nsz + n]     = make_float2(c[0]+bb.x+r0.x, c[1]+bb.y+r0.y);
                *(float2*)&CpF[(size_t)(m+8) * Nsz + n] = make_float2(c[2]+bb.x+r1.x, c[3]+bb.y+r1.y);
            } else if (EPI == 7) {
                float2 bb = *(const float2*)&bias[n];
                __nv_bfloat162 p0 = __floats2bfloat162_rn(c[0]+bb.x, c[1]+bb.y);
                __nv_bfloat162 p1 = __floats2bfloat162_rn(c[2]+bb.x, c[3]+bb.y);
                *(__nv_bfloat162*)&CpH[(size_t)m * Nsz + n]     = p0;
                *(__nv_bfloat162*)&CpH[(size_t)(m+8) * Nsz + n] = p1;
            } else {  // EPI == 6: bias(m) + xnT_flat + x_flat, write x1
                size_t f0 = (size_t)m * Ln + n;
                size_t f1 = (size_t)(m+8) * Ln + n;
                float2 t0 = *(const float2*)&respZ[f0];
                float2 t1 = *(const float2*)&respZ[f1];
                float2 u0 = *(const float2*)&res2Z[f0];
                float2 u1 = *(const float2*)&res2Z[f1];
                *(float2*)&CpF[f0] = make_float2(c[0]+bm0+t0.x+u0.x, c[1]+bm0+t0.y+u0.y);
                *(float2*)&CpF[f1] = make_float2(c[2]+bm1+t1.x+u1.x, c[3]+bm1+t1.y+u1.y);
            }
        }
    }
}

// ---------------- fused prep: all weight cvt + bias concat + ctx/ksum zero ---
// unit = 4 elements. Regions (in 4-elem units):
//   [0, 65536)          wq   -> wqkvb[0:]
//   [65536, 131072)     wk   -> wqkvb[Cn*Cn:]
//   [131072, 196608)    wv   -> wqkvb[2*Cn*Cn:]
//   [196608, 262144)    wr   -> wrb
//   [262144, 524288)    fc1  -> f1b
//   [524288, 786432)    fc2  -> f2b
//   [786432, 786816)    bq|bk|bv -> bqkv (1536 f32 = 384 units)
//   [786816, 852352)    ctx zero (CTXN = 262144 floats = 65536 units)
//   [852352, 853376)    ksum zero (4096 floats = 1024 units)
#define PREP_UNITS 853376
__global__ void prep_kernel(const float* __restrict__ wq, const float* __restrict__ wk,
                            const float* __restrict__ wv, const float* __restrict__ wr,
                            const float* __restrict__ f1, const float* __restrict__ f2,
                            const float* __restrict__ bq, const float* __restrict__ bk,
                            const float* __restrict__ bv,
                            __nv_bfloat16* __restrict__ wqkvb,
                            __nv_bfloat16* __restrict__ wrb, __nv_bfloat16* __restrict__ f1b,
                            __nv_bfloat16* __restrict__ f2b, float* __restrict__ bqkv,
                            float* __restrict__ ctx, float* __restrict__ ksum) {
    int u = blockIdx.x * blockDim.x + threadIdx.x;
    const float* src;
    __nv_bfloat16* dst;
    int off;
    if (u < 65536)        { src = wq; dst = wqkvb; off = u; }
    else if (u < 131072)  { src = wk; dst = wqkvb + (size_t)Cn*Cn;   off = u - 65536; }
    else if (u < 196608)  { src = wv; dst = wqkvb + (size_t)2*Cn*Cn; off = u - 131072; }
    else if (u < 262144)  { src = wr; dst = wrb;  off = u - 196608; }
    else if (u < 524288)  { src = f1; dst = f1b;  off = u - 262144; }
    else if (u < 786432)  { src = f2; dst = f2b;  off = u - 524288; }
    else if (u < 786816)  {
        int i = (u - 786432) * 4;
        #pragma unroll
        for (int j = 0; j < 4; j++) {
            int k = i + j;
            bqkv[k] = (k < Cn) ? bq[k] : (k < 2*Cn ? bk[k - Cn] : bv[k - 2*Cn]);
        }
        return;
    } else if (u < 852352) {
        int i = (u - 786816) * 4;
        *(float4*)&ctx[i] = make_float4(0.f, 0.f, 0.f, 0.f);
        return;
    } else if (u < 853376) {
        int i = (u - 852352) * 4;
        *(float4*)&ksum[i] = make_float4(0.f, 0.f, 0.f, 0.f);
        return;
    } else return;
    int i = off * 4;
    float4 v = *(const float4*)(src + i);
    *(__nv_bfloat162*)(dst + i)     = __floats2bfloat162_rn(v.x, v.y);
    *(__nv_bfloat162*)(dst + i + 2) = __floats2bfloat162_rn(v.z, v.w);
}

// ------- fused LN1(x) + transpose: writes xnb (bf16, (B,L,C)) + xnT (f32, (B,C,L))
#define LNX_PITCH 513
#define LNX_SMEM  (32 * LNX_PITCH * 4)   // 65,664 B
__global__ __launch_bounds__(1024)
void ln_x_kernel(const float* __restrict__ in, const float* __restrict__ w,
                 const float* __restrict__ b, __nv_bfloat16* __restrict__ outb,
                 float* __restrict__ outT) {
    extern __shared__ float s[];
    int tid = threadIdx.x;
    int wrp = tid >> 5, lane = tid & 31;
    int row0 = blockIdx.x * 32;
    int row = row0 + wrp;
    size_t base = (size_t)row * Cn;

    float4 v[4];
    float sum = 0.f;
    #pragma unroll
    for (int j = 0; j < 4; j++) {
        v[j] = *(const float4*)(in + base + lane * 4 + j * 128);
        sum += v[j].x + v[j].y + v[j].z + v[j].w;
    }
    #pragma unroll
    for (int o = 16; o > 0; o >>= 1) sum += __shfl_xor_sync(0xffffffffu, sum, o);
    float mean = sum * (1.0f / Cn);
    float vs = 0.f;
    #pragma unroll
    for (int j = 0; j < 4; j++) {
        float d0 = v[j].x - mean, d1 = v[j].y - mean, d2 = v[j].z - mean, d3 = v[j].w - mean;
        vs += d0*d0 + d1*d1 + d2*d2 + d3*d3;
    }
    #pragma unroll
    for (int o = 16; o > 0; o >>= 1) vs += __shfl_xor_sync(0xffffffffu, vs, o);
    float rs = rsqrtf(vs * (1.0f / Cn) + 1e-5f);

    float* srow = s + wrp * LNX_PITCH;
    #pragma unroll
    for (int j = 0; j < 4; j++) {
        int c = lane * 4 + j * 128;
        float4 ww = *(const float4*)(w + c);
        float4 bb = *(const float4*)(b + c);
        float o0 = (v[j].x - mean) * rs * ww.x + bb.x;
        float o1 = (v[j].y - mean) * rs * ww.y + bb.y;
        float o2 = (v[j].z - mean) * rs * ww.z + bb.z;
        float o3 = (v[j].w - mean) * rs * ww.w + bb.w;
        *(__nv_bfloat162*)(outb + base + c)     = __floats2bfloat162_rn(o0, o1);
        *(__nv_bfloat162*)(outb + base + c + 2) = __floats2bfloat162_rn(o2, o3);
        srow[c] = o0; srow[c+1] = o1; srow[c+2] = o2; srow[c+3] = o3;
    }
    __syncthreads();

    int bz = row0 / Ln;
    int lb = row0 - bz * Ln;
    float* op = outT + (size_t)bz * Cn * Ln + lb;
    #pragma unroll
    for (int it = 0; it < 4; it++) {
        int idx = it * 1024 + tid;
        int c = idx >> 3, p = idx & 7;
        int l = p * 4;
        float4 ov = make_float4(s[(l+0) * LNX_PITCH + c], s[(l+1) * LNX_PITCH + c],
                                s[(l+2) * LNX_PITCH + c], s[(l+3) * LNX_PITCH + c]);
        *(float4*)(op + (size_t)c * Ln + l) = ov;
    }
}

// ---------------- LayerNorm (plain, bf16 out) --------------------------------
__global__ void ln_kernel(const float* __restrict__ in, const float* __restrict__ w,
                          const float* __restrict__ b, __nv_bfloat16* __restrict__ outb) {
    __shared__ float s8[8];
    int row = blockIdx.x, t = threadIdx.x;
    size_t base = (size_t)row * Cn;
    float v0 = in[base + t], v1 = in[base + t + 256];
    float mean = blockReduceSum256(v0 + v1, s8, t) * (1.0f / Cn);
    float d0 = v0 - mean, d1 = v1 - mean;
    float var = blockReduceSum256(d0*d0 + d1*d1, s8, t) * (1.0f / Cn);
    float rs = rsqrtf(var + 1e-5f);
    outb[base + t]       = __float2bfloat16_rn(d0 * rs * w[t]       + b[t]);
    outb[base + t + 256] = __float2bfloat16_rn(d1 * rs * w[t + 256] + b[t + 256]);
}

// ------- context[b,h,k,v] += sum_l exp(k) * val  (UNNORMALIZED) --------------
// Also accumulates per-channel sum of exp(k) into ksum (for agg normalization).
__global__ __launch_bounds__(256)
void context_kernel(const __nv_bfloat16* __restrict__ qkvb,
                    float* __restrict__ ctx, float* __restrict__ ksum) {
    __shared__ float sK[8][64];
    __shared__ float sV[8][64];
    __shared__ float red[8][64];
    int b = blockIdx.z, h = blockIdx.y;
    int l0 = blockIdx.x * (Ln / 16);
    int tid = threadIdx.x;
    int tx = tid & 15, ty = tid >> 4;
    int li = tid >> 5, cc = tid & 31;

    float psA = 0.f, psB = 0.f;
    float acc[4][4] = {};
    for (int lc = l0; lc < l0 + Ln / 16; lc += 8) {
        size_t idx = ((size_t)(b * Ln + lc + li)) * QKV + Cn + h * DK + cc;  // k
        float eA = fexp(__bfloat162float(qkvb[idx]));
        float eB = fexp(__bfloat162float(qkvb[idx + 32]));
        sK[li][cc]      = eA;  psA += eA;
        sK[li][cc + 32] = eB;  psB += eB;
        sV[li][cc]      = __bfloat162float(qkvb[idx + Cn]);        // v = k + Cn
        sV[li][cc + 32] = __bfloat162float(qkvb[idx + Cn + 32]);
        __syncthreads();
        #pragma unroll
        for (int l = 0; l < 8; l++) {
            float kvv[4], vv[4];
            #pragma unroll
            for (int i = 0; i < 4; i++) { kvv[i] = sK[l][ty*4+i]; vv[i] = sV[l][tx*4+i]; }
            #pragma unroll
            for (int i = 0; i < 4; i++)
                #pragma unroll
                for (int j = 0; j < 4; j++) acc[i][j] = fmaf(kvv[i], vv[j], acc[i][j]);
        }
        __syncthreads();
    }

    // per-channel exp-sum reduce across the 8 li groups, one atomic per channel
    red[li][cc] = psA;
    red[li][cc + 32] = psB;
    __syncthreads();
    if (li == 0) {
        float sA = 0.f, sB = 0.f;
        #pragma unroll
        for (int i = 0; i < 8; i++) { sA += red[i][cc]; sB += red[i][cc + 32]; }
        atomicAdd(&ksum[b * Cn + h * DK + cc], sA);
        atomicAdd(&ksum[b * Cn + h * DK + cc + 32], sB);
    }

    size_t cb = (size_t)(b * Hn + h) * DK * DK;
    #pragma unroll
    for (int i = 0; i < 4; i++)
        #pragma unroll
        for (int j = 0; j < 4; j++)
            atomicAdd(&ctx[cb + (size_t)(ty*4+i) * DK + tx*4+j], acc[i][j]);
}

// ---- aggT[b, l, h*64+v] = sum_k (ctx[b,h,k,v]/ksum[k]) * softmax_k(q) ------
__global__ __launch_bounds__(256)
void agg_kernel(const __nv_bfloat16* __restrict__ qkvb, const float* __restrict__ ctx,
                const float* __restrict__ ksum, __nv_bfloat16* __restrict__ aggT) {
    __shared__ float sC[64][64];
    __shared__ float sQ[128][65];   // padded: conflict-free row access
    __shared__ float sZ[64];
    int b = blockIdx.z, h = blockIdx.y, l0 = blockIdx.x * 128;
    int tid = threadIdx.x;
    int tx = tid & 15, ty = tid >> 4;

    if (tid < 64) sZ[tid] = 1.0f / ksum[b * Cn + h * DK + tid];
    __syncthreads();

    size_t cb = (size_t)(b * Hn + h) * DK * DK;
    for (int f = tid; f < 4096; f += 256) sC[f >> 6][f & 63] = ctx[cb + f] * sZ[f >> 6];
    for (int f = tid; f < 8192; f += 256) {
        int l = f >> 6, kk = f & 63;
        sQ[l][kk] = __bfloat162float(qkvb[((size_t)(b * Ln + l0 + l)) * QKV + h * DK + kk]);
    }
    __syncthreads();

    // in-block q softmax over the 64 channels of this head (2 threads/row)
    {
        int r = tid >> 1;
        int off = (tid & 1) * 32;
        float s = 0.f;
        #pragma unroll
        for (int j = 0; j < 32; j++) {
            float e = fexp(sQ[r][off + j]);
            sQ[r][off + j] = e;
            s += e;
        }
        s += __shfl_xor_sync(0xffffffffu, s, 1);
        float inv = 1.0f / s;
        #pragma unroll
        for (int j = 0; j < 32; j++) sQ[r][off + j] *= inv;
    }
    __syncthreads();

    float acc[4][8] = {};
    #pragma unroll
    for (int k = 0; k < 64; k++) {
        float cv[4], qv[8];
        #pragma unroll
        for (int i = 0; i < 4; i++) cv[i] = sC[k][tx*4+i];
        #pragma unroll
        for (int j = 0; j < 8; j++) qv[j] = sQ[ty*8+j][k];
        #pragma unroll
        for (int i = 0; i < 4; i++)
            #pragma unroll
            for (int j = 0; j < 8; j++) acc[i][j] = fmaf(cv[i], qv[j], acc[i][j]);
    }
    #pragma unroll
    for (int j = 0; j < 8; j++) {
        size_t ob = ((size_t)(b * Ln + l0 + ty*8 + j)) * Cn + h * DK + tx*4;
        *(__nv_bfloat162*)&aggT[ob]     = __floats2bfloat162_rn(acc[0][j], acc[1][j]);
        *(__nv_bfloat162*)&aggT[ob + 2] = __floats2bfloat162_rn(acc[2][j], acc[3][j]);
    }
}

// ---------------- host launcher ---------------------------------------------
extern "C" void kernel_launch(void* const* d_in, const int* in_sizes, int n_in,
                              void* d_out, int out_size) {
    (void)in_sizes; (void)n_in; (void)out_size;
    const float* x     = (const float*)d_in[0];
    const float* v     = (const float*)d_in[1];
    const float* ln1_w = (const float*)d_in[4];
    const float* ln1_b = (const float*)d_in[5];
    const float* lnv_w = (const float*)d_in[6];
    const float* lnv_b = (const float*)d_in[7];
    const float* ln2_w = (const float*)d_in[8];
    const float* ln2_b = (const float*)d_in[9];
    const float* wq    = (const float*)d_in[10];
    const float* bq    = (const float*)d_in[11];
    const float* wk    = (const float*)d_in[12];
    const float* bk    = (const float*)d_in[13];
    const float* wv    = (const float*)d_in[14];
    const float* bv    = (const float*)d_in[15];
    const float* wr    = (const float*)d_in[16];
    const float* br    = (const float*)d_in[17];
    const float* fc1_w = (const float*)d_in[18];
    const float* fc1_b = (const float*)d_in[19];
    const float* fc2_w = (const float*)d_in[20];
    const float* fc2_b = (const float*)d_in[21];
    float* out = (float*)d_out;

    float *p_xnT, *p_ksum, *p_ctx, *p_x1, *p_bqkv;
    __nv_bfloat16 *p_xnb, *p_vnb, *p_qkvb, *p_aggT, *p_x1nb, *p_h1b;
    __nv_bfloat16 *p_wqkvb, *p_wrb, *p_f1b, *p_f2b;
    cudaGetSymbolAddress((void**)&p_xnT, g_xnT);
    cudaGetSymbolAddress((void**)&p_xnb, g_xnb);
    cudaGetSymbolAddress((void**)&p_vnb, g_vnb);
    cudaGetSymbolAddress((void**)&p_qkvb,g_qkvb);
    cudaGetSymbolAddress((void**)&p_ksum,g_ksum);
    cudaGetSymbolAddress((void**)&p_ctx, g_ctx);
    cudaGetSymbolAddress((void**)&p_aggT,g_aggT);
    cudaGetSymbolAddress((void**)&p_x1,  g_x1);
    cudaGetSymbolAddress((void**)&p_x1nb,g_x1nb);
    cudaGetSymbolAddress((void**)&p_h1b, g_h1b);
    cudaGetSymbolAddress((void**)&p_wqkvb,g_wqkvb);
    cudaGetSymbolAddress((void**)&p_wrb, g_wrb);
    cudaGetSymbolAddress((void**)&p_f1b, g_f1b);
    cudaGetSymbolAddress((void**)&p_f2b, g_f2b);
    cudaGetSymbolAddress((void**)&p_bqkv,g_bqkv);

    cudaFuncSetAttribute(gemm_bf16<1>, cudaFuncAttributeMaxDynamicSharedMemorySize, SMEM_REQ);
    cudaFuncSetAttribute(gemm_bf16<2>, cudaFuncAttributeMaxDynamicSharedMemorySize, SMEM_REQ);
    cudaFuncSetAttribute(gemm_bf16<6>, cudaFuncAttributeMaxDynamicSharedMemorySize, SMEM_REQ);
    cudaFuncSetAttribute(gemm_bf16<7>, cudaFuncAttributeMaxDynamicSharedMemorySize, SMEM_REQ);
    cudaFuncSetAttribute(ln_x_kernel, cudaFuncAttributeMaxDynamicSharedMemorySize, LNX_SMEM);

    // 0) fused prep: weight conversions + bias concat + ctx & ksum zero
    prep_kernel<<<(PREP_UNITS + 255)/256, 256>>>(wq, wk, wv, wr, fc1_w, fc2_w,
                                                 bq, bk, bv,
                                                 p_wqkvb, p_wrb, p_f1b, p_f2b,
                                                 p_bqkv, p_ctx, p_ksum);

    // 1) LN1(x) fused with transpose (-> xnb bf16 + xnT f32); LN(v) plain
    ln_x_kernel<<<Mrows / 32, 1024, LNX_SMEM>>>(x, ln1_w, ln1_b, p_xnb, p_xnT);
    ln_kernel<<<Mrows, 256>>>(v, lnv_w, lnv_b, p_vnb);

    // 2) fused q|k|v projection (N=1536; A chosen per n-block)
    gemm_bf16<7><<<dim3(QKV / 128, Mrows / 128), 256, SMEM_REQ>>>(
        p_xnb, p_wqkvb, p_bqkv, (const float*)p_vnb, nullptr, p_qkvb, Mrows, QKV, Cn);

    // 3) context = sum_l exp(k)·val (unnormalized) + ksum accumulation
    context_kernel<<<dim3(16, Hn, Bn), 256>>>(p_qkvb, p_ctx, p_ksum);

    // 4) aggT = ((ctx/ksum)^T @ softmax(q))^T  -> (B, L, C) bf16
    agg_kernel<<<dim3(Ln / 128, Hn, Bn), 256>>>(p_qkvb, p_ctx, p_ksum, p_aggT);

    // 5) reproj fused: x1 = wr·aggT + br + xnT + x   (writes x1 directly)
    gemm_bf16<6><<<dim3(Ln / 128, Cn / 128, Bn), 256, SMEM_REQ>>>(
        p_wrb, p_aggT, br, p_xnT, x, p_x1, Cn, Ln, Cn);

    // 6) x1n = LN(x1) (bf16)
    ln_kernel<<<Mrows, 256>>>(p_x1, ln2_w, ln2_b, p_x1nb);

    // 7) MLP
    gemm_bf16<1><<<dim3(HID / 128, Mrows / 128), 256, SMEM_REQ>>>(
        p_x1nb, p_f1b, fc1_b, nullptr, nullptr, p_h1b, Mrows, HID, Cn);
    gemm_bf16<2><<<dim3(Cn / 128, Mrows / 128), 256, SMEM_REQ>>>(
        p_h1b, p_f2b, fc2_b, p_x1, nullptr, out, Mrows, Cn, HID);
}

// round 15
// speedup vs baseline: 1.2628x; 1.0939x over previous
#include <cuda_runtime.h>
#include <cuda_bf16.h>
#include <math.h>
#include <stdint.h>

#define Bn   8
#define Ln   9216
#define Cn   512
#define Hn   8
#define DK   64
#define HID  2048
#define Mrows (Bn*Ln)          // 73728
#define QKV  1536              // fused q|k|v width
#define CTXN (Bn*Hn*DK*DK)     // 262144 floats

// ---------------- scratch (device globals: no runtime allocation) ----------
__device__ float          g_xnT [Mrows*Cn];   // fp32 xn transposed (B,C,L)
__device__ __nv_bfloat16  g_xnb [Mrows*Cn];   // bf16 xn (GEMM A)
__device__ __nv_bfloat16  g_vnb [Mrows*Cn];   // bf16 vn (GEMM A)
__device__ __nv_bfloat16  g_qkvb[Mrows*QKV];  // bf16 fused [q | k | v]
__device__ float          g_ksum[Bn*Cn];      // per-(b,ck) sum of exp(k) over L
__device__ float          g_ctx [CTXN];       // UNNORMALIZED context
__device__ __nv_bfloat16  g_aggT[Mrows*Cn];   // (B, L, C) bf16 (reproj B operand)
__device__ float          g_x1  [Mrows*Cn];   // x1 = reproj + br + xn^T + x (flat)
__device__ __nv_bfloat16  g_x1nb[Mrows*Cn];   // bf16 LN2 out (fc1 A)
__device__ __nv_bfloat16  g_h1b [Mrows*HID];  // bf16 gelu(fc1) (fc2 A)
// bf16 weights
__device__ __nv_bfloat16  g_wqkvb[QKV*Cn];    // [wq ; wk ; wv]
__device__ __nv_bfloat16  g_wrb  [Cn*Cn];
__device__ __nv_bfloat16  g_f1b  [HID*Cn];
__device__ __nv_bfloat16  g_f2b  [Cn*HID];
__device__ float          g_bqkv [QKV];       // [bq ; bk ; bv]

// ---------------- asm helpers ------------------------------------------------
__device__ __forceinline__ uint32_t smem_u32(const void* p) {
    uint32_t a;
    asm("{ .reg .u64 t; cvta.to.shared.u64 t, %1; cvt.u32.u64 %0, t; }" : "=r"(a) : "l"(p));
    return a;
}
__device__ __forceinline__ void ldsm4(uint32_t* r, uint32_t a) {
    asm volatile("ldmatrix.sync.aligned.m8n8.x4.shared.b16 {%0,%1,%2,%3}, [%4];"
        : "=r"(r[0]), "=r"(r[1]), "=r"(r[2]), "=r"(r[3]) : "r"(a));
}
__device__ __forceinline__ void ldsm4t(uint32_t* r, uint32_t a) {
    asm volatile("ldmatrix.sync.aligned.m8n8.x4.trans.shared.b16 {%0,%1,%2,%3}, [%4];"
        : "=r"(r[0]), "=r"(r[1]), "=r"(r[2]), "=r"(r[3]) : "r"(a));
}
__device__ __forceinline__ void mma_bf16(float* c, const uint32_t* a, const uint32_t* b) {
    asm volatile("mma.sync.aligned.m16n8k16.row.col.f32.bf16.bf16.f32 "
        "{%0,%1,%2,%3}, {%4,%5,%6,%7}, {%8,%9}, {%0,%1,%2,%3};"
        : "+f"(c[0]), "+f"(c[1]), "+f"(c[2]), "+f"(c[3])
        : "r"(a[0]), "r"(a[1]), "r"(a[2]), "r"(a[3]), "r"(b[0]), "r"(b[1]));
}
__device__ __forceinline__ void cp16(uint32_t dst, const void* src) {
    asm volatile("cp.async.cg.shared.global [%0], [%1], 16;" :: "r"(dst), "l"(src));
}
#define CP_COMMIT() asm volatile("cp.async.commit_group;" ::: "memory")
#define CP_WAIT2()  asm volatile("cp.async.wait_group 2;" ::: "memory")

// smem tile geometry: rows of 32 bf16 (64B) padded to 80B -> conflict-free LDSM
#define ROWB   80
#define STG_A  (128*ROWB)          // 10240
#define STG    (2*STG_A)           // 20480 per stage
#define NST    4
#define SMEM_REQ (NST*STG)         // 81920  (2 CTAs/SM)

// ---------------- misc device helpers ---------------------------------------
__device__ __forceinline__ float gelu_exact(float x) {
    return 0.5f * x * (1.0f + erff(x * 0.70710678118654752f));
}

// fast exp in the FMA pipe (no MUFU): exp(x) = 2^(x*log2e)
__device__ __forceinline__ float fexp(float x) {
    x = fmaxf(x, -60.0f);
    float y = x * 1.4426950408889634f;
    float t = y + 12582912.0f;            // 1.5 * 2^23
    float n = t - 12582912.0f;            // round(y)
    float r = y - n;                      // [-0.5, 0.5]
    float p = fmaf(0.0013333558f, r, 0.0096181298f);
    p = fmaf(p, r, 0.0555041087f);
    p = fmaf(p, r, 0.2402265070f);
    p = fmaf(p, r, 0.6931471806f);
    p = fmaf(p, r, 1.0f);
    int ni = (int)n;
    return p * __int_as_float((ni + 127) << 23);
}

__device__ __forceinline__ float blockReduceSum256(float v, float* s8, int tid) {
    #pragma unroll
    for (int o = 16; o > 0; o >>= 1) v += __shfl_xor_sync(0xffffffffu, v, o);
    int lane = tid & 31, w = tid >> 5;
    if (lane == 0) s8[w] = v;
    __syncthreads();
    if (w == 0) {
        v = (lane < 8) ? s8[lane] : 0.f;
        #pragma unroll
        for (int o = 4; o > 0; o >>= 1) v += __shfl_xor_sync(0xffffffffu, v, o);
        if (lane == 0) s8[0] = v;
    }
    __syncthreads();
    float r = s8[0];
    __syncthreads();
    return r;
}

// ---------------- bf16 GEMM (NT): C[M,N] = A[M,K]·W[N,K]^T + epilogue -------
// EPI: 1 bias(n)+gelu -> bf16    2 bias(n)+res -> f32
//      6 reproj fused: bias(m) + res(xnT flat) + res2(x flat) -> x1 (f32)
//      7 qkv: bias(n) -> bf16; A = (n0 < Cn) ? A : (bf16*)res
template<int EPI>
__global__ __launch_bounds__(256)
void gemm_bf16(const __nv_bfloat16* __restrict__ A, const __nv_bfloat16* __restrict__ W,
               const float* __restrict__ bias, const float* __restrict__ res,
               const float* __restrict__ res2,
               void* __restrict__ Cout, int Msz, int Nsz, int Ksz) {
    extern __shared__ char smem[];
    uint32_t sbase = smem_u32(smem);

    int tid = threadIdx.x;
    int wid = tid >> 5, lane = tid & 31;
    int m0 = blockIdx.y * 128, n0 = blockIdx.x * 128;
    int wm = (wid & 1) * 64, wn = (wid >> 1) * 32;
    int lrow = lane & 15;
    int lko  = (lane >> 4) * 16;

    const __nv_bfloat16* Aop = A;
    const __nv_bfloat16* Wop = W;
    const float* respZ = res;
    const float* res2Z = res2;
    float* CpF = (float*)Cout;
    __nv_bfloat16* CpH = (__nv_bfloat16*)Cout;
    if (EPI == 7) {
        if (n0 >= Cn) Aop = (const __nv_bfloat16*)res;   // k|v columns use vn
    }
    if (EPI == 6) {
        size_t z = blockIdx.z;
        size_t zoff = z * (size_t)Cn * Ln;
        Wop   = W + z * (size_t)Ln * Cn;
        respZ = res + zoff;
        res2Z = res2 + zoff;
        CpF   = (float*)Cout + zoff;
    }

    float acc[4][4][4];
    #pragma unroll
    for (int i = 0; i < 4; i++)
        #pragma unroll
        for (int j = 0; j < 4; j++)
            #pragma unroll
            for (int c = 0; c < 4; c++) acc[i][j][c] = 0.f;

    int arow = tid >> 2;
    int acol = tid & 3;

    auto load_chunk = [&](int kt, int s) {
        uint32_t dA = sbase + s * STG;
        uint32_t dB = dA + STG_A;
        const __nv_bfloat16* ga = Aop + (size_t)(m0 + arow) * Ksz + kt * 32 + acol * 8;
        cp16(dA + (uint32_t)(arow * ROWB + acol * 16), ga);
        cp16(dA + (uint32_t)((arow + 64) * ROWB + acol * 16), ga + (size_t)64 * Ksz);
        const __nv_bfloat16* gb = Wop + (size_t)(n0 + arow) * Ksz + kt * 32 + acol * 8;
        cp16(dB + (uint32_t)(arow * ROWB + acol * 16), gb);
        cp16(dB + (uint32_t)((arow + 64) * ROWB + acol * 16), gb + (size_t)64 * Ksz);
        CP_COMMIT();
    };

    int nk = Ksz >> 5;
    load_chunk(0, 0);
    load_chunk(1, 1);
    load_chunk(2, 2);

    for (int kt = 0; kt < nk; kt++) {
        int s = kt & 3;
        CP_WAIT2();
        __syncthreads();
        if (kt + 3 < nk) load_chunk(kt + 3, (kt + 3) & 3);
        else CP_COMMIT();

        uint32_t sA = sbase + s * STG;
        uint32_t sB = sA + STG_A;
        #pragma unroll
        for (int ks = 0; ks < 2; ks++) {
            uint32_t af[4][4], bf[2][4];
            #pragma unroll
            for (int mt = 0; mt < 4; mt++)
                ldsm4(af[mt], sA + (uint32_t)((wm + mt*16 + lrow) * ROWB + ks*32 + lko));
            #pragma unroll
            for (int g = 0; g < 2; g++)
                ldsm4(bf[g], sB + (uint32_t)((wn + g*16 + lrow) * ROWB + ks*32 + lko));
            #pragma unroll
            for (int mt = 0; mt < 4; mt++)
                #pragma unroll
                for (int nt = 0; nt < 4; nt++) {
                    uint32_t bb[2] = { bf[nt>>1][nt&1], bf[nt>>1][(nt&1) + 2] };
                    mma_bf16(acc[mt][nt], af[mt], bb);
                }
        }
    }

    int rm = lane >> 2, cn = (lane & 3) * 2;
    #pragma unroll
    for (int mt = 0; mt < 4; mt++) {
        int m = m0 + wm + mt*16 + rm;
        float bm0 = 0.f, bm1 = 0.f;
        if (EPI == 6) { bm0 = bias[m]; bm1 = bias[m + 8]; }
        #pragma unroll
        for (int nt = 0; nt < 4; nt++) {
            int n = n0 + wn + nt*8 + cn;
            float* c = acc[mt][nt];
            if (EPI == 1) {
                float2 bb = *(const float2*)&bias[n];
                __nv_bfloat162 p0 = __floats2bfloat162_rn(gelu_exact(c[0]+bb.x), gelu_exact(c[1]+bb.y));
                __nv_bfloat162 p1 = __floats2bfloat162_rn(gelu_exact(c[2]+bb.x), gelu_exact(c[3]+bb.y));
                *(__nv_bfloat162*)&CpH[(size_t)m * Nsz + n]     = p0;
                *(__nv_bfloat162*)&CpH[(size_t)(m+8) * Nsz + n] = p1;
            } else if (EPI == 2) {
                float2 bb = *(const float2*)&bias[n];
                float2 r0 = *(const float2*)&respZ[(size_t)m * Nsz + n];
                float2 r1 = *(const float2*)&respZ[(size_t)(m+8) * Nsz + n];
                *(float2*)&CpF[(size_t)m * Nsz + n]     = make_float2(c[0]+bb.x+r0.x, c[1]+bb.y+r0.y);
                *(float2*)&CpF[(size_t)(m+8) * Nsz + n] = make_float2(c[2]+bb.x+r1.x, c[3]+bb.y+r1.y);
            } else if (EPI == 7) {
                float2 bb = *(const float2*)&bias[n];
                __nv_bfloat162 p0 = __floats2bfloat162_rn(c[0]+bb.x, c[1]+bb.y);
                __nv_bfloat162 p1 = __floats2bfloat162_rn(c[2]+bb.x, c[3]+bb.y);
                *(__nv_bfloat162*)&CpH[(size_t)m * Nsz + n]     = p0;
                *(__nv_bfloat162*)&CpH[(size_t)(m+8) * Nsz + n] = p1;
            } else {  // EPI == 6
                size_t f0 = (size_t)m * Ln + n;
                size_t f1 = (size_t)(m+8) * Ln + n;
                float2 t0 = *(const float2*)&respZ[f0];
                float2 t1 = *(const float2*)&respZ[f1];
                float2 u0 = *(const float2*)&res2Z[f0];
                float2 u1 = *(const float2*)&res2Z[f1];
                *(float2*)&CpF[f0] = make_float2(c[0]+bm0+t0.x+u0.x, c[1]+bm0+t0.y+u0.y);
                *(float2*)&CpF[f1] = make_float2(c[2]+bm1+t1.x+u1.x, c[3]+bm1+t1.y+u1.y);
            }
        }
    }
}

// ---------------- fused prep ------------------------------------------------
#define PREP_UNITS 853376
__global__ void prep_kernel(const float* __restrict__ wq, const float* __restrict__ wk,
                            const float* __restrict__ wv, const float* __restrict__ wr,
                            const float* __restrict__ f1, const float* __restrict__ f2,
                            const float* __restrict__ bq, const float* __restrict__ bk,
                            const float* __restrict__ bv,
                            __nv_bfloat16* __restrict__ wqkvb,
                            __nv_bfloat16* __restrict__ wrb, __nv_bfloat16* __restrict__ f1b,
                            __nv_bfloat16* __restrict__ f2b, float* __restrict__ bqkv,
                            float* __restrict__ ctx, float* __restrict__ ksum) {
    int u = blockIdx.x * blockDim.x + threadIdx.x;
    const float* src;
    __nv_bfloat16* dst;
    int off;
    if (u < 65536)        { src = wq; dst = wqkvb; off = u; }
    else if (u < 131072)  { src = wk; dst = wqkvb + (size_t)Cn*Cn;   off = u - 65536; }
    else if (u < 196608)  { src = wv; dst = wqkvb + (size_t)2*Cn*Cn; off = u - 131072; }
    else if (u < 262144)  { src = wr; dst = wrb;  off = u - 196608; }
    else if (u < 524288)  { src = f1; dst = f1b;  off = u - 262144; }
    else if (u < 786432)  { src = f2; dst = f2b;  off = u - 524288; }
    else if (u < 786816)  {
        int i = (u - 786432) * 4;
        #pragma unroll
        for (int j = 0; j < 4; j++) {
            int k = i + j;
            bqkv[k] = (k < Cn) ? bq[k] : (k < 2*Cn ? bk[k - Cn] : bv[k - 2*Cn]);
        }
        return;
    } else if (u < 852352) {
        int i = (u - 786816) * 4;
        *(float4*)&ctx[i] = make_float4(0.f, 0.f, 0.f, 0.f);
        return;
    } else if (u < 853376) {
        int i = (u - 852352) * 4;
        *(float4*)&ksum[i] = make_float4(0.f, 0.f, 0.f, 0.f);
        return;
    } else return;
    int i = off * 4;
    float4 v = *(const float4*)(src + i);
    *(__nv_bfloat162*)(dst + i)     = __floats2bfloat162_rn(v.x, v.y);
    *(__nv_bfloat162*)(dst + i + 2) = __floats2bfloat162_rn(v.z, v.w);
}

// ------- fused LN1(x) + transpose -------------------------------------------
#define LNX_PITCH 513
#define LNX_SMEM  (32 * LNX_PITCH * 4)
__global__ __launch_bounds__(1024)
void ln_x_kernel(const float* __restrict__ in, const float* __restrict__ w,
                 const float* __restrict__ b, __nv_bfloat16* __restrict__ outb,
                 float* __restrict__ outT) {
    extern __shared__ float s[];
    int tid = threadIdx.x;
    int wrp = tid >> 5, lane = tid & 31;
    int row0 = blockIdx.x * 32;
    int row = row0 + wrp;
    size_t base = (size_t)row * Cn;

    float4 v[4];
    float sum = 0.f;
    #pragma unroll
    for (int j = 0; j < 4; j++) {
        v[j] = *(const float4*)(in + base + lane * 4 + j * 128);
        sum += v[j].x + v[j].y + v[j].z + v[j].w;
    }
    #pragma unroll
    for (int o = 16; o > 0; o >>= 1) sum += __shfl_xor_sync(0xffffffffu, sum, o);
    float mean = sum * (1.0f / Cn);
    float vs = 0.f;
    #pragma unroll
    for (int j = 0; j < 4; j++) {
        float d0 = v[j].x - mean, d1 = v[j].y - mean, d2 = v[j].z - mean, d3 = v[j].w - mean;
        vs += d0*d0 + d1*d1 + d2*d2 + d3*d3;
    }
    #pragma unroll
    for (int o = 16; o > 0; o >>= 1) vs += __shfl_xor_sync(0xffffffffu, vs, o);
    float rs = rsqrtf(vs * (1.0f / Cn) + 1e-5f);

    float* srow = s + wrp * LNX_PITCH;
    #pragma unroll
    for (int j = 0; j < 4; j++) {
        int c = lane * 4 + j * 128;
        float4 ww = *(const float4*)(w + c);
        float4 bb = *(const float4*)(b + c);
        float o0 = (v[j].x - mean) * rs * ww.x + bb.x;
        float o1 = (v[j].y - mean) * rs * ww.y + bb.y;
        float o2 = (v[j].z - mean) * rs * ww.z + bb.z;
        float o3 = (v[j].w - mean) * rs * ww.w + bb.w;
        *(__nv_bfloat162*)(outb + base + c)     = __floats2bfloat162_rn(o0, o1);
        *(__nv_bfloat162*)(outb + base + c + 2) = __floats2bfloat162_rn(o2, o3);
        srow[c] = o0; srow[c+1] = o1; srow[c+2] = o2; srow[c+3] = o3;
    }
    __syncthreads();

    int bz = row0 / Ln;
    int lb = row0 - bz * Ln;
    float* op = outT + (size_t)bz * Cn * Ln + lb;
    #pragma unroll
    for (int it = 0; it < 4; it++) {
        int idx = it * 1024 + tid;
        int c = idx >> 3, p = idx & 7;
        int l = p * 4;
        float4 ov = make_float4(s[(l+0) * LNX_PITCH + c], s[(l+1) * LNX_PITCH + c],
                                s[(l+2) * LNX_PITCH + c], s[(l+3) * LNX_PITCH + c]);
        *(float4*)(op + (size_t)c * Ln + l) = ov;
    }
}

// ---------------- LayerNorm (plain, bf16 out) --------------------------------
__global__ void ln_kernel(const float* __restrict__ in, const float* __restrict__ w,
                          const float* __restrict__ b, __nv_bfloat16* __restrict__ outb) {
    __shared__ float s8[8];
    int row = blockIdx.x, t = threadIdx.x;
    size_t base = (size_t)row * Cn;
    float v0 = in[base + t], v1 = in[base + t + 256];
    float mean = blockReduceSum256(v0 + v1, s8, t) * (1.0f / Cn);
    float d0 = v0 - mean, d1 = v1 - mean;
    float var = blockReduceSum256(d0*d0 + d1*d1, s8, t) * (1.0f / Cn);
    float rs = rsqrtf(var + 1e-5f);
    outb[base + t]       = __float2bfloat16_rn(d0 * rs * w[t]       + b[t]);
    outb[base + t + 256] = __float2bfloat16_rn(d1 * rs * w[t + 256] + b[t + 256]);
}

// ------- context (tensorized): ctx[64kk,64vv] += EK^T · V over l -------------
// smem [l][ch] tiles, stride 72 bf16 (144B); fragments via ldmatrix.x4.trans.
#define CSTR 72
__global__ __launch_bounds__(256)
void context_kernel(const __nv_bfloat16* __restrict__ qkvb,
                    float* __restrict__ ctx, float* __restrict__ ksum) {
    __shared__ __nv_bfloat16 sEK[64*CSTR];
    __shared__ __nv_bfloat16 sV [64*CSTR];
    __shared__ float red[64];
    int b = blockIdx.z, h = blockIdx.y;
    int l0 = blockIdx.x * (Ln / 16);          // 576 l per block, 9 chunks of 64
    int tid = threadIdx.x;
    int wid = tid >> 5, lane = tid & 31;
    int r0 = tid >> 3;            // 0..31 (l row)
    int sg = tid & 7;             // 8-channel segment
    if (tid < 64) red[tid] = 0.f;

    int wm = (wid & 3) * 16;      // kk chunk
    int wn = (wid >> 2) * 32;     // vv chunk
    // trans-ldsm lane addressing: source l row + channel chunk
    int tr = (lane & 7) + ((lane >> 4) << 3);
    int tc = ((lane >> 3) & 1) * 8;

    uint32_t ekb = smem_u32(sEK);
    uint32_t vb  = smem_u32(sV);

    float ps[8] = {};
    float acc[4][4] = {};

    for (int c = 0; c < 9; c++) {
        int lc = l0 + c * 64;
        #pragma unroll
        for (int rr = 0; rr < 2; rr++) {
            int r = r0 + rr * 32;
            const __nv_bfloat16* gk = qkvb + ((size_t)(b * Ln + lc + r)) * QKV + Cn + h * DK + sg * 8;
            uint4 kraw = *(const uint4*)gk;
            uint4 vraw = *(const uint4*)(gk + Cn);
            __nv_bfloat16 tmp[8], eo[8];
            *(uint4*)tmp = kraw;
            #pragma unroll
            for (int j = 0; j < 8; j++) {
                float e = fexp(__bfloat162float(tmp[j]));
                ps[j] += e;
                eo[j] = __float2bfloat16_rn(e);
            }
            *(uint4*)&sEK[r * CSTR + sg * 8] = *(uint4*)eo;
            *(uint4*)&sV [r * CSTR + sg * 8] = vraw;
        }
        __syncthreads();
        #pragma unroll
        for (int ks = 0; ks < 4; ks++) {
            uint32_t af[4], bf[2][4];
            uint32_t rowoff = (uint32_t)((ks * 16 + tr) * CSTR * 2);
            ldsm4t(af,    ekb + rowoff + (uint32_t)((wm + tc) * 2));
            ldsm4t(bf[0], vb  + rowoff + (uint32_t)((wn + tc) * 2));
            ldsm4t(bf[1], vb  + rowoff + (uint32_t)((wn + 16 + tc) * 2));
            #pragma unroll
            for (int nt = 0; nt < 4; nt++) {
                uint32_t bb[2] = { bf[nt>>1][nt&1], bf[nt>>1][(nt&1) + 2] };
                mma_bf16(acc[nt], af, bb);
            }
        }
        __syncthreads();
    }

    // ksum reduce (channels fixed per thread: sg*8 + j)
    #pragma unroll
    for (int j = 0; j < 8; j++) atomicAdd(&red[sg * 8 + j], ps[j]);
    __syncthreads();
    if (tid < 64) atomicAdd(&ksum[b * Cn + h * DK + tid], red[tid]);

    // ctx atomics: C rows = kk (wm..wm+15), cols = vv (wn + nt*8)
    int rm = lane >> 2, cnq = (lane & 3) * 2;
    size_t cb = (size_t)(b * Hn + h) * DK * DK;
    #pragma unroll
    for (int nt = 0; nt < 4; nt++) {
        int n = wn + nt * 8 + cnq;
        float* cc = acc[nt];
        atomicAdd(&ctx[cb + (size_t)(wm + rm) * DK + n],       cc[0]);
        atomicAdd(&ctx[cb + (size_t)(wm + rm) * DK + n + 1],   cc[1]);
        atomicAdd(&ctx[cb + (size_t)(wm + rm + 8) * DK + n],   cc[2]);
        atomicAdd(&ctx[cb + (size_t)(wm + rm + 8) * DK + n+1], cc[3]);
    }
}

// ---- agg (tensorized): aggT[l, ch] = P[l,kk] · ctxn^T[kk,vv] ----------------
// P (softmaxed q) bf16 in smem [l][kk]; ctxn transposed to [vv][kk] bf16.
__global__ __launch_bounds__(256)
void agg_kernel(const __nv_bfloat16* __restrict__ qkvb, const float* __restrict__ ctx,
                const float* __restrict__ ksum, __nv_bfloat16* __restrict__ aggT) {
    __shared__ __nv_bfloat16 sP [128*CSTR];   // [l][kk]
    __shared__ __nv_bfloat16 sCt[64*CSTR];    // [vv][kk]
    __shared__ float sZ[64];
    int b = blockIdx.z, h = blockIdx.y, l0 = blockIdx.x * 128;
    int tid = threadIdx.x;
    int wid = tid >> 5, lane = tid & 31;

    if (tid < 64) sZ[tid] = 1.0f / ksum[b * Cn + h * DK + tid];
    __syncthreads();

    size_t cb = (size_t)(b * Hn + h) * DK * DK;
    for (int f = tid; f < 4096; f += 256) {
        int kk = f >> 6, vv = f & 63;
        sCt[vv * CSTR + kk] = __float2bfloat16_rn(ctx[cb + f] * sZ[kk]);
    }

    // build P: thread handles half-row (32 channels) of q
    {
        int r = tid >> 1;
        int off = (tid & 1) * 32;
        const __nv_bfloat16* gq = qkvb + ((size_t)(b * Ln + l0 + r)) * QKV + h * DK + off;
        __nv_bfloat16 qv[32];
        *(uint4*)&qv[0]  = *(const uint4*)(gq);
        *(uint4*)&qv[8]  = *(const uint4*)(gq + 8);
        *(uint4*)&qv[16] = *(const uint4*)(gq + 16);
        *(uint4*)&qv[24] = *(const uint4*)(gq + 24);
        float e[32];
        float s = 0.f;
        #pragma unroll
        for (int j = 0; j < 32; j++) {
            e[j] = fexp(__bfloat162float(qv[j]));
            s += e[j];
        }
        s += __shfl_xor_sync(0xffffffffu, s, 1);
        float inv = 1.0f / s;
        __nv_bfloat16* pp = &sP[r * CSTR + off];
        #pragma unroll
        for (int j = 0; j < 32; j += 2)
            *(__nv_bfloat162*)(pp + j) = __floats2bfloat162_rn(e[j] * inv, e[j+1] * inv);
    }
    __syncthreads();

    // mma: warp tile 32(l) x 32(vv)
    int wm = (wid & 3) * 32, wn = (wid >> 2) * 32;
    int lrow = lane & 15, lko = (lane >> 4) * 16;
    uint32_t pb = smem_u32(sP), ctb = smem_u32(sCt);
    float acc[2][4][4] = {};
    #pragma unroll
    for (int ks = 0; ks < 2; ks++) {     // kk chunks of 32 bytes... K=64 -> 2x k32? no: k16 steps
        // K = 64 kk -> 4 k16 steps; handle as 2 outer x 2 inner via byte offsets
    }
    #pragma unroll
    for (int ks = 0; ks < 4; ks++) {     // 4 k16 steps over kk
        uint32_t koff = (uint32_t)(ks * 32 + lko);
        uint32_t af[2][4], bf[2][4];
        #pragma unroll
        for (int mt = 0; mt < 2; mt++)
            ldsm4(af[mt], pb + (uint32_t)((wm + mt*16 + lrow) * CSTR * 2) + koff);
        #pragma unroll
        for (int g = 0; g < 2; g++)
            ldsm4(bf[g], ctb + (uint32_t)((wn + g*16 + lrow) * CSTR * 2) + koff);
        #pragma unroll
        for (int mt = 0; mt < 2; mt++)
            #pragma unroll
            for (int nt = 0; nt < 4; nt++) {
                uint32_t bb[2] = { bf[nt>>1][nt&1], bf[nt>>1][(nt&1) + 2] };
                mma_bf16(acc[mt][nt], af[mt], bb);
            }
    }

    // epilogue: bf16 stores to aggT (B, L, C)
    int rm = lane >> 2, cnq = (lane & 3) * 2;
    #pragma unroll
    for (int mt = 0; mt < 2; mt++) {
        int l = wm + mt * 16 + rm;
        size_t ob0 = ((size_t)(b * Ln + l0 + l)) * Cn + h * DK;
        size_t ob1 = ((size_t)(b * Ln + l0 + l + 8)) * Cn + h * DK;
        #pragma unroll
        for (int nt = 0; nt < 4; nt++) {
            int n = wn + nt * 8 + cnq;
            float* cc = acc[mt][nt];
            *(__nv_bfloat162*)&aggT[ob0 + n] = __floats2bfloat162_rn(cc[0], cc[1]);
            *(__nv_bfloat162*)&aggT[ob1 + n] = __floats2bfloat162_rn(cc[2], cc[3]);
        }
    }
}

// ---------------- host launcher ---------------------------------------------
extern "C" void kernel_launch(void* const* d_in, const int* in_sizes, int n_in,
                              void* d_out, int out_size) {
    (void)in_sizes; (void)n_in; (void)out_size;
    const float* x     = (const float*)d_in[0];
    const float* v     = (const float*)d_in[1];
    const float* ln1_w = (const float*)d_in[4];
    const float* ln1_b = (const float*)d_in[5];
    const float* lnv_w = (const float*)d_in[6];
    const float* lnv_b = (const float*)d_in[7];
    const float* ln2_w = (const float*)d_in[8];
    const float* ln2_b = (const float*)d_in[9];
    const float* wq    = (const float*)d_in[10];
    const float* bq    = (const float*)d_in[11];
    const float* wk    = (const float*)d_in[12];
    const float* bk    = (const float*)d_in[13];
    const float* wv    = (const float*)d_in[14];
    const float* bv    = (const float*)d_in[15];
    const float* wr    = (const float*)d_in[16];
    const float* br    = (const float*)d_in[17];
    const float* fc1_w = (const float*)d_in[18];
    const float* fc1_b = (const float*)d_in[19];
    const float* fc2_w = (const float*)d_in[20];
    const float* fc2_b = (const float*)d_in[21];
    float* out = (float*)d_out;

    float *p_xnT, *p_ksum, *p_ctx, *p_x1, *p_bqkv;
    __nv_bfloat16 *p_xnb, *p_vnb, *p_qkvb, *p_aggT, *p_x1nb, *p_h1b;
    __nv_bfloat16 *p_wqkvb, *p_wrb, *p_f1b, *p_f2b;
    cudaGetSymbolAddress((void**)&p_xnT, g_xnT);
    cudaGetSymbolAddress((void**)&p_xnb, g_xnb);
    cudaGetSymbolAddress((void**)&p_vnb, g_vnb);
    cudaGetSymbolAddress((void**)&p_qkvb,g_qkvb);
    cudaGetSymbolAddress((void**)&p_ksum,g_ksum);
    cudaGetSymbolAddress((void**)&p_ctx, g_ctx);
    cudaGetSymbolAddress((void**)&p_aggT,g_aggT);
    cudaGetSymbolAddress((void**)&p_x1,  g_x1);
    cudaGetSymbolAddress((void**)&p_x1nb,g_x1nb);
    cudaGetSymbolAddress((void**)&p_h1b, g_h1b);
    cudaGetSymbolAddress((void**)&p_wqkvb,g_wqkvb);
    cudaGetSymbolAddress((void**)&p_wrb, g_wrb);
    cudaGetSymbolAddress((void**)&p_f1b, g_f1b);
    cudaGetSymbolAddress((void**)&p_f2b, g_f2b);
    cudaGetSymbolAddress((void**)&p_bqkv,g_bqkv);

    cudaFuncSetAttribute(gemm_bf16<1>, cudaFuncAttributeMaxDynamicSharedMemorySize, SMEM_REQ);
    cudaFuncSetAttribute(gemm_bf16<2>, cudaFuncAttributeMaxDynamicSharedMemorySize, SMEM_REQ);
    cudaFuncSetAttribute(gemm_bf16<6>, cudaFuncAttributeMaxDynamicSharedMemorySize, SMEM_REQ);
    cudaFuncSetAttribute(gemm_bf16<7>, cudaFuncAttributeMaxDynamicSharedMemorySize, SMEM_REQ);
    cudaFuncSetAttribute(ln_x_kernel, cudaFuncAttributeMaxDynamicSharedMemorySize, LNX_SMEM);

    // 0) fused prep: weight conversions + bias concat + ctx & ksum zero
    prep_kernel<<<(PREP_UNITS + 255)/256, 256>>>(wq, wk, wv, wr, fc1_w, fc2_w,
                                                 bq, bk, bv,
                                                 p_wqkvb, p_wrb, p_f1b, p_f2b,
                                                 p_bqkv, p_ctx, p_ksum);

    // 1) LN1(x) fused with transpose (-> xnb bf16 + xnT f32); LN(v) plain
    ln_x_kernel<<<Mrows / 32, 1024, LNX_SMEM>>>(x, ln1_w, ln1_b, p_xnb, p_xnT);
    ln_kernel<<<Mrows, 256>>>(v, lnv_w, lnv_b, p_vnb);

    // 2) fused q|k|v projection (N=1536; A chosen per n-block)
    gemm_bf16<7><<<dim3(QKV / 128, Mrows / 128), 256, SMEM_REQ>>>(
        p_xnb, p_wqkvb, p_bqkv, (const float*)p_vnb, nullptr, p_qkvb, Mrows, QKV, Cn);

    // 3) context = sum_l exp(k)·val (unnormalized, tensorized) + ksum
    context_kernel<<<dim3(16, Hn, Bn), 256>>>(p_qkvb, p_ctx, p_ksum);

    // 4) aggT = softmax(q) @ (ctx/ksum)  -> (B, L, C) bf16 (tensorized)
    agg_kernel<<<dim3(Ln / 128, Hn, Bn), 256>>>(p_qkvb, p_ctx, p_ksum, p_aggT);

    // 5) reproj fused: x1 = wr·aggT + br + xnT + x
    gemm_bf16<6><<<dim3(Ln / 128, Cn / 128, Bn), 256, SMEM_REQ>>>(
        p_wrb, p_aggT, br, p_xnT, x, p_x1, Cn, Ln, Cn);

    // 6) x1n = LN(x1) (bf16)
    ln_kernel<<<Mrows, 256>>>(p_x1, ln2_w, ln2_b, p_x1nb);

    // 7) MLP
    gemm_bf16<1><<<dim3(HID / 128, Mrows / 128), 256, SMEM_REQ>>>(
        p_x1nb, p_f1b, fc1_b, nullptr, nullptr, p_h1b, Mrows, HID, Cn);
    gemm_bf16<2><<<dim3(Cn / 128, Mrows / 128), 256, SMEM_REQ>>>(
        p_h1b, p_f2b, fc2_b, p_x1, nullptr, out, Mrows, Cn, HID);
}

// round 16
// speedup vs baseline: 1.3171x; 1.0430x over previous
#include <cuda_runtime.h>
#include <cuda_bf16.h>
#include <math.h>
#include <stdint.h>

#define Bn   8
#define Ln   9216
#define Cn   512
#define Hn   8
#define DK   64
#define HID  2048
#define Mrows (Bn*Ln)          // 73728
#define QKV  1536              // fused q|k|v width
#define CTXN (Bn*Hn*DK*DK)     // 262144 floats

// ---------------- scratch (device globals: no runtime allocation) ----------
__device__ float          g_xnT [Mrows*Cn];   // fp32 xn transposed (B,C,L)
__device__ __nv_bfloat16  g_xnb [Mrows*Cn];   // bf16 xn (GEMM A)
__device__ __nv_bfloat16  g_vnb [Mrows*Cn];   // bf16 vn (GEMM A)
__device__ __nv_bfloat16  g_qkvb[Mrows*QKV];  // bf16 fused [q | k | v]
__device__ float          g_ksum[Bn*Cn];      // per-(b,ck) sum of exp(k) over L
__device__ float          g_ctx [CTXN];       // UNNORMALIZED context
__device__ __nv_bfloat16  g_aggT[Mrows*Cn];   // (B, L, C) bf16 (reproj B operand)
__device__ float          g_x1  [Mrows*Cn];   // x1 = reproj + br + xn^T + x (flat)
__device__ __nv_bfloat16  g_x1nb[Mrows*Cn];   // bf16 LN2 out (fc1 A)
__device__ __nv_bfloat16  g_h1b [Mrows*HID];  // bf16 gelu(fc1) (fc2 A)
// bf16 weights
__device__ __nv_bfloat16  g_wqkvb[QKV*Cn];    // [wq ; wk ; wv]
__device__ __nv_bfloat16  g_wrb  [Cn*Cn];
__device__ __nv_bfloat16  g_f1b  [HID*Cn];
__device__ __nv_bfloat16  g_f2b  [Cn*HID];
__device__ float          g_bqkv [QKV];       // [bq ; bk ; bv]

// ---------------- asm helpers ------------------------------------------------
__device__ __forceinline__ uint32_t smem_u32(const void* p) {
    uint32_t a;
    asm("{ .reg .u64 t; cvta.to.shared.u64 t, %1; cvt.u32.u64 %0, t; }" : "=r"(a) : "l"(p));
    return a;
}
__device__ __forceinline__ void ldsm4(uint32_t* r, uint32_t a) {
    asm volatile("ldmatrix.sync.aligned.m8n8.x4.shared.b16 {%0,%1,%2,%3}, [%4];"
        : "=r"(r[0]), "=r"(r[1]), "=r"(r[2]), "=r"(r[3]) : "r"(a));
}
__device__ __forceinline__ void ldsm4t(uint32_t* r, uint32_t a) {
    asm volatile("ldmatrix.sync.aligned.m8n8.x4.trans.shared.b16 {%0,%1,%2,%3}, [%4];"
        : "=r"(r[0]), "=r"(r[1]), "=r"(r[2]), "=r"(r[3]) : "r"(a));
}
__device__ __forceinline__ void mma_bf16(float* c, const uint32_t* a, const uint32_t* b) {
    asm volatile("mma.sync.aligned.m16n8k16.row.col.f32.bf16.bf16.f32 "
        "{%0,%1,%2,%3}, {%4,%5,%6,%7}, {%8,%9}, {%0,%1,%2,%3};"
        : "+f"(c[0]), "+f"(c[1]), "+f"(c[2]), "+f"(c[3])
        : "r"(a[0]), "r"(a[1]), "r"(a[2]), "r"(a[3]), "r"(b[0]), "r"(b[1]));
}
__device__ __forceinline__ void cp16(uint32_t dst, const void* src) {
    asm volatile("cp.async.cg.shared.global [%0], [%1], 16;" :: "r"(dst), "l"(src));
}
#define CP_COMMIT() asm volatile("cp.async.commit_group;" ::: "memory")
#define CP_WAIT2()  asm volatile("cp.async.wait_group 2;" ::: "memory")

// smem tile geometry: rows of 32 bf16 (64B) padded to 80B -> conflict-free LDSM
#define ROWB   80
#define STG_A  (128*ROWB)          // 10240
#define STG    (2*STG_A)           // 20480 per stage
#define NST    4
#define SMEM_REQ (NST*STG)         // 81920  (2 CTAs/SM)

// ---------------- misc device helpers ---------------------------------------
__device__ __forceinline__ float gelu_exact(float x) {
    return 0.5f * x * (1.0f + erff(x * 0.70710678118654752f));
}

// fast exp in the FMA pipe (no MUFU): exp(x) = 2^(x*log2e)
__device__ __forceinline__ float fexp(float x) {
    x = fmaxf(x, -60.0f);
    float y = x * 1.4426950408889634f;
    float t = y + 12582912.0f;            // 1.5 * 2^23
    float n = t - 12582912.0f;            // round(y)
    float r = y - n;                      // [-0.5, 0.5]
    float p = fmaf(0.0013333558f, r, 0.0096181298f);
    p = fmaf(p, r, 0.0555041087f);
    p = fmaf(p, r, 0.2402265070f);
    p = fmaf(p, r, 0.6931471806f);
    p = fmaf(p, r, 1.0f);
    int ni = (int)n;
    return p * __int_as_float((ni + 127) << 23);
}

// ---------------- bf16 GEMM (NT): C[M,N] = A[M,K]·W[N,K]^T + epilogue -------
// EPI: 1 bias(n)+gelu -> bf16    2 bias(n)+res -> f32
//      6 reproj fused: bias(m) + res(xnT flat) + res2(x flat) -> x1 (f32)
//      7 qkv: bias(n) -> bf16; A = (n0 < Cn) ? A : (bf16*)res
template<int EPI>
__global__ __launch_bounds__(256)
void gemm_bf16(const __nv_bfloat16* __restrict__ A, const __nv_bfloat16* __restrict__ W,
               const float* __restrict__ bias, const float* __restrict__ res,
               const float* __restrict__ res2,
               void* __restrict__ Cout, int Msz, int Nsz, int Ksz) {
    extern __shared__ char smem[];
    uint32_t sbase = smem_u32(smem);

    int tid = threadIdx.x;
    int wid = tid >> 5, lane = tid & 31;
    int m0 = blockIdx.y * 128, n0 = blockIdx.x * 128;
    int wm = (wid & 1) * 64, wn = (wid >> 1) * 32;
    int lrow = lane & 15;
    int lko  = (lane >> 4) * 16;

    const __nv_bfloat16* Aop = A;
    const __nv_bfloat16* Wop = W;
    const float* respZ = res;
    const float* res2Z = res2;
    float* CpF = (float*)Cout;
    __nv_bfloat16* CpH = (__nv_bfloat16*)Cout;
    if (EPI == 7) {
        if (n0 >= Cn) Aop = (const __nv_bfloat16*)res;   // k|v columns use vn
    }
    if (EPI == 6) {
        size_t z = blockIdx.z;
        size_t zoff = z * (size_t)Cn * Ln;
        Wop   = W + z * (size_t)Ln * Cn;
        respZ = res + zoff;
        res2Z = res2 + zoff;
        CpF   = (float*)Cout + zoff;
    }

    float acc[4][4][4];
    #pragma unroll
    for (int i = 0; i < 4; i++)
        #pragma unroll
        for (int j = 0; j < 4; j++)
            #pragma unroll
            for (int c = 0; c < 4; c++) acc[i][j][c] = 0.f;

    int arow = tid >> 2;
    int acol = tid & 3;

    auto load_chunk = [&](int kt, int s) {
        uint32_t dA = sbase + s * STG;
        uint32_t dB = dA + STG_A;
        const __nv_bfloat16* ga = Aop + (size_t)(m0 + arow) * Ksz + kt * 32 + acol * 8;
        cp16(dA + (uint32_t)(arow * ROWB + acol * 16), ga);
        cp16(dA + (uint32_t)((arow + 64) * ROWB + acol * 16), ga + (size_t)64 * Ksz);
        const __nv_bfloat16* gb = Wop + (size_t)(n0 + arow) * Ksz + kt * 32 + acol * 8;
        cp16(dB + (uint32_t)(arow * ROWB + acol * 16), gb);
        cp16(dB + (uint32_t)((arow + 64) * ROWB + acol * 16), gb + (size_t)64 * Ksz);
        CP_COMMIT();
    };

    int nk = Ksz >> 5;
    load_chunk(0, 0);
    load_chunk(1, 1);
    load_chunk(2, 2);

    for (int kt = 0; kt < nk; kt++) {
        int s = kt & 3;
        CP_WAIT2();
        __syncthreads();
        if (kt + 3 < nk) load_chunk(kt + 3, (kt + 3) & 3);
        else CP_COMMIT();

        uint32_t sA = sbase + s * STG;
        uint32_t sB = sA + STG_A;
        #pragma unroll
        for (int ks = 0; ks < 2; ks++) {
            uint32_t af[4][4], bf[2][4];
            #pragma unroll
            for (int mt = 0; mt < 4; mt++)
                ldsm4(af[mt], sA + (uint32_t)((wm + mt*16 + lrow) * ROWB + ks*32 + lko));
            #pragma unroll
            for (int g = 0; g < 2; g++)
                ldsm4(bf[g], sB + (uint32_t)((wn + g*16 + lrow) * ROWB + ks*32 + lko));
            #pragma unroll
            for (int mt = 0; mt < 4; mt++)
                #pragma unroll
                for (int nt = 0; nt < 4; nt++) {
                    uint32_t bb[2] = { bf[nt>>1][nt&1], bf[nt>>1][(nt&1) + 2] };
                    mma_bf16(acc[mt][nt], af[mt], bb);
                }
        }
    }

    int rm = lane >> 2, cn = (lane & 3) * 2;
    #pragma unroll
    for (int mt = 0; mt < 4; mt++) {
        int m = m0 + wm + mt*16 + rm;
        float bm0 = 0.f, bm1 = 0.f;
        if (EPI == 6) { bm0 = bias[m]; bm1 = bias[m + 8]; }
        #pragma unroll
        for (int nt = 0; nt < 4; nt++) {
            int n = n0 + wn + nt*8 + cn;
            float* c = acc[mt][nt];
            if (EPI == 1) {
                float2 bb = *(const float2*)&bias[n];
                __nv_bfloat162 p0 = __floats2bfloat162_rn(gelu_exact(c[0]+bb.x), gelu_exact(c[1]+bb.y));
                __nv_bfloat162 p1 = __floats2bfloat162_rn(gelu_exact(c[2]+bb.x), gelu_exact(c[3]+bb.y));
                *(__nv_bfloat162*)&CpH[(size_t)m * Nsz + n]     = p0;
                *(__nv_bfloat162*)&CpH[(size_t)(m+8) * Nsz + n] = p1;
            } else if (EPI == 2) {
                float2 bb = *(const float2*)&bias[n];
                float2 r0 = *(const float2*)&respZ[(size_t)m * Nsz + n];
                float2 r1 = *(const float2*)&respZ[(size_t)(m+8) * Nsz + n];
                *(float2*)&CpF[(size_t)m * Nsz + n]     = make_float2(c[0]+bb.x+r0.x, c[1]+bb.y+r0.y);
                *(float2*)&CpF[(size_t)(m+8) * Nsz + n] = make_float2(c[2]+bb.x+r1.x, c[3]+bb.y+r1.y);
            } else if (EPI == 7) {
                float2 bb = *(const float2*)&bias[n];
                __nv_bfloat162 p0 = __floats2bfloat162_rn(c[0]+bb.x, c[1]+bb.y);
                __nv_bfloat162 p1 = __floats2bfloat162_rn(c[2]+bb.x, c[3]+bb.y);
                *(__nv_bfloat162*)&CpH[(size_t)m * Nsz + n]     = p0;
                *(__nv_bfloat162*)&CpH[(size_t)(m+8) * Nsz + n] = p1;
            } else {  // EPI == 6
                size_t f0 = (size_t)m * Ln + n;
                size_t f1 = (size_t)(m+8) * Ln + n;
                float2 t0 = *(const float2*)&respZ[f0];
                float2 t1 = *(const float2*)&respZ[f1];
                float2 u0 = *(const float2*)&res2Z[f0];
                float2 u1 = *(const float2*)&res2Z[f1];
                *(float2*)&CpF[f0] = make_float2(c[0]+bm0+t0.x+u0.x, c[1]+bm0+t0.y+u0.y);
                *(float2*)&CpF[f1] = make_float2(c[2]+bm1+t1.x+u1.x, c[3]+bm1+t1.y+u1.y);
            }
        }
    }
}

// ---------------- fused prep ------------------------------------------------
#define PREP_UNITS 853376
__global__ void prep_kernel(const float* __restrict__ wq, const float* __restrict__ wk,
                            const float* __restrict__ wv, const float* __restrict__ wr,
                            const float* __restrict__ f1, const float* __restrict__ f2,
                            const float* __restrict__ bq, const float* __restrict__ bk,
                            const float* __restrict__ bv,
                            __nv_bfloat16* __restrict__ wqkvb,
                            __nv_bfloat16* __restrict__ wrb, __nv_bfloat16* __restrict__ f1b,
                            __nv_bfloat16* __restrict__ f2b, float* __restrict__ bqkv,
                            float* __restrict__ ctx, float* __restrict__ ksum) {
    int u = blockIdx.x * blockDim.x + threadIdx.x;
    const float* src;
    __nv_bfloat16* dst;
    int off;
    if (u < 65536)        { src = wq; dst = wqkvb; off = u; }
    else if (u < 131072)  { src = wk; dst = wqkvb + (size_t)Cn*Cn;   off = u - 65536; }
    else if (u < 196608)  { src = wv; dst = wqkvb + (size_t)2*Cn*Cn; off = u - 131072; }
    else if (u < 262144)  { src = wr; dst = wrb;  off = u - 196608; }
    else if (u < 524288)  { src = f1; dst = f1b;  off = u - 262144; }
    else if (u < 786432)  { src = f2; dst = f2b;  off = u - 524288; }
    else if (u < 786816)  {
        int i = (u - 786432) * 4;
        #pragma unroll
        for (int j = 0; j < 4; j++) {
            int k = i + j;
            bqkv[k] = (k < Cn) ? bq[k] : (k < 2*Cn ? bk[k - Cn] : bv[k - 2*Cn]);
        }
        return;
    } else if (u < 852352) {
        int i = (u - 786816) * 4;
        *(float4*)&ctx[i] = make_float4(0.f, 0.f, 0.f, 0.f);
        return;
    } else if (u < 853376) {
        int i = (u - 852352) * 4;
        *(float4*)&ksum[i] = make_float4(0.f, 0.f, 0.f, 0.f);
        return;
    } else return;
    int i = off * 4;
    float4 v = *(const float4*)(src + i);
    *(__nv_bfloat162*)(dst + i)     = __floats2bfloat162_rn(v.x, v.y);
    *(__nv_bfloat162*)(dst + i + 2) = __floats2bfloat162_rn(v.z, v.w);
}

// ------- fused LN1(x) + transpose -------------------------------------------
#define LNX_PITCH 513
#define LNX_SMEM  (32 * LNX_PITCH * 4)
__global__ __launch_bounds__(1024)
void ln_x_kernel(const float* __restrict__ in, const float* __restrict__ w,
                 const float* __restrict__ b, __nv_bfloat16* __restrict__ outb,
                 float* __restrict__ outT) {
    extern __shared__ float s[];
    int tid = threadIdx.x;
    int wrp = tid >> 5, lane = tid & 31;
    int row0 = blockIdx.x * 32;
    int row = row0 + wrp;
    size_t base = (size_t)row * Cn;

    float4 v[4];
    float sum = 0.f;
    #pragma unroll
    for (int j = 0; j < 4; j++) {
        v[j] = *(const float4*)(in + base + lane * 4 + j * 128);
        sum += v[j].x + v[j].y + v[j].z + v[j].w;
    }
    #pragma unroll
    for (int o = 16; o > 0; o >>= 1) sum += __shfl_xor_sync(0xffffffffu, sum, o);
    float mean = sum * (1.0f / Cn);
    float vs = 0.f;
    #pragma unroll
    for (int j = 0; j < 4; j++) {
        float d0 = v[j].x - mean, d1 = v[j].y - mean, d2 = v[j].z - mean, d3 = v[j].w - mean;
        vs += d0*d0 + d1*d1 + d2*d2 + d3*d3;
    }
    #pragma unroll
    for (int o = 16; o > 0; o >>= 1) vs += __shfl_xor_sync(0xffffffffu, vs, o);
    float rs = rsqrtf(vs * (1.0f / Cn) + 1e-5f);

    float* srow = s + wrp * LNX_PITCH;
    #pragma unroll
    for (int j = 0; j < 4; j++) {
        int c = lane * 4 + j * 128;
        float4 ww = *(const float4*)(w + c);
        float4 bb = *(const float4*)(b + c);
        float o0 = (v[j].x - mean) * rs * ww.x + bb.x;
        float o1 = (v[j].y - mean) * rs * ww.y + bb.y;
        float o2 = (v[j].z - mean) * rs * ww.z + bb.z;
        float o3 = (v[j].w - mean) * rs * ww.w + bb.w;
        *(__nv_bfloat162*)(outb + base + c)     = __floats2bfloat162_rn(o0, o1);
        *(__nv_bfloat162*)(outb + base + c + 2) = __floats2bfloat162_rn(o2, o3);
        srow[c] = o0; srow[c+1] = o1; srow[c+2] = o2; srow[c+3] = o3;
    }
    __syncthreads();

    int bz = row0 / Ln;
    int lb = row0 - bz * Ln;
    float* op = outT + (size_t)bz * Cn * Ln + lb;
    #pragma unroll
    for (int it = 0; it < 4; it++) {
        int idx = it * 1024 + tid;
        int c = idx >> 3, p = idx & 7;
        int l = p * 4;
        float4 ov = make_float4(s[(l+0) * LNX_PITCH + c], s[(l+1) * LNX_PITCH + c],
                                s[(l+2) * LNX_PITCH + c], s[(l+3) * LNX_PITCH + c]);
        *(float4*)(op + (size_t)c * Ln + l) = ov;
    }
}

// ---------------- warp-per-row LayerNorm (bf16 out, no block barriers) -------
__global__ __launch_bounds__(1024)
void ln_warp_kernel(const float* __restrict__ in, const float* __restrict__ w,
                    const float* __restrict__ b, __nv_bfloat16* __restrict__ outb) {
    int tid = threadIdx.x;
    int wrp = tid >> 5, lane = tid & 31;
    int row = blockIdx.x * 32 + wrp;
    size_t base = (size_t)row * Cn;

    float4 v[4];
    float sum = 0.f;
    #pragma unroll
    for (int j = 0; j < 4; j++) {
        v[j] = *(const float4*)(in + base + lane * 4 + j * 128);
        sum += v[j].x + v[j].y + v[j].z + v[j].w;
    }
    #pragma unroll
    for (int o = 16; o > 0; o >>= 1) sum += __shfl_xor_sync(0xffffffffu, sum, o);
    float mean = sum * (1.0f / Cn);
    float vs = 0.f;
    #pragma unroll
    for (int j = 0; j < 4; j++) {
        float d0 = v[j].x - mean, d1 = v[j].y - mean, d2 = v[j].z - mean, d3 = v[j].w - mean;
        vs += d0*d0 + d1*d1 + d2*d2 + d3*d3;
    }
    #pragma unroll
    for (int o = 16; o > 0; o >>= 1) vs += __shfl_xor_sync(0xffffffffu, vs, o);
    float rs = rsqrtf(vs * (1.0f / Cn) + 1e-5f);

    #pragma unroll
    for (int j = 0; j < 4; j++) {
        int c = lane * 4 + j * 128;
        float4 ww = *(const float4*)(w + c);
        float4 bb = *(const float4*)(b + c);
        float o0 = (v[j].x - mean) * rs * ww.x + bb.x;
        float o1 = (v[j].y - mean) * rs * ww.y + bb.y;
        float o2 = (v[j].z - mean) * rs * ww.z + bb.z;
        float o3 = (v[j].w - mean) * rs * ww.w + bb.w;
        *(__nv_bfloat162*)(outb + base + c)     = __floats2bfloat162_rn(o0, o1);
        *(__nv_bfloat162*)(outb + base + c + 2) = __floats2bfloat162_rn(o2, o3);
    }
}

// ------- context (tensorized): ctx[64kk,64vv] += EK^T · V over l -------------
#define CSTR 72
__global__ __launch_bounds__(256)
void context_kernel(const __nv_bfloat16* __restrict__ qkvb,
                    float* __restrict__ ctx, float* __restrict__ ksum) {
    __shared__ __nv_bfloat16 sEK[64*CSTR];
    __shared__ __nv_bfloat16 sV [64*CSTR];
    __shared__ float red[64];
    int b = blockIdx.z, h = blockIdx.y;
    int l0 = blockIdx.x * (Ln / 16);          // 576 l per block, 9 chunks of 64
    int tid = threadIdx.x;
    int wid = tid >> 5, lane = tid & 31;
    int r0 = tid >> 3;            // 0..31 (l row)
    int sg = tid & 7;             // 8-channel segment
    if (tid < 64) red[tid] = 0.f;

    int wm = (wid & 3) * 16;      // kk chunk
    int wn = (wid >> 2) * 32;     // vv chunk
    int tr = (lane & 7) + ((lane >> 4) << 3);
    int tc = ((lane >> 3) & 1) * 8;

    uint32_t ekb = smem_u32(sEK);
    uint32_t vb  = smem_u32(sV);

    float ps[8] = {};
    float acc[4][4] = {};

    for (int c = 0; c < 9; c++) {
        int lc = l0 + c * 64;
        #pragma unroll
        for (int rr = 0; rr < 2; rr++) {
            int r = r0 + rr * 32;
            const __nv_bfloat16* gk = qkvb + ((size_t)(b * Ln + lc + r)) * QKV + Cn + h * DK + sg * 8;
            uint4 kraw = *(const uint4*)gk;
            uint4 vraw = *(const uint4*)(gk + Cn);
            __nv_bfloat16 tmp[8], eo[8];
            *(uint4*)tmp = kraw;
            #pragma unroll
            for (int j = 0; j < 8; j++) {
                float e = fexp(__bfloat162float(tmp[j]));
                ps[j] += e;
                eo[j] = __float2bfloat16_rn(e);
            }
            *(uint4*)&sEK[r * CSTR + sg * 8] = *(uint4*)eo;
            *(uint4*)&sV [r * CSTR + sg * 8] = vraw;
        }
        __syncthreads();
        #pragma unroll
        for (int ks = 0; ks < 4; ks++) {
            uint32_t af[4], bf[2][4];
            uint32_t rowoff = (uint32_t)((ks * 16 + tr) * CSTR * 2);
            ldsm4t(af,    ekb + rowoff + (uint32_t)((wm + tc) * 2));
            ldsm4t(bf[0], vb  + rowoff + (uint32_t)((wn + tc) * 2));
            ldsm4t(bf[1], vb  + rowoff + (uint32_t)((wn + 16 + tc) * 2));
            #pragma unroll
            for (int nt = 0; nt < 4; nt++) {
                uint32_t bb[2] = { bf[nt>>1][nt&1], bf[nt>>1][(nt&1) + 2] };
                mma_bf16(acc[nt], af, bb);
            }
        }
        __syncthreads();
    }

    #pragma unroll
    for (int j = 0; j < 8; j++) atomicAdd(&red[sg * 8 + j], ps[j]);
    __syncthreads();
    if (tid < 64) atomicAdd(&ksum[b * Cn + h * DK + tid], red[tid]);

    int rm = lane >> 2, cnq = (lane & 3) * 2;
    size_t cb = (size_t)(b * Hn + h) * DK * DK;
    #pragma unroll
    for (int nt = 0; nt < 4; nt++) {
        int n = wn + nt * 8 + cnq;
        float* cc = acc[nt];
        atomicAdd(&ctx[cb + (size_t)(wm + rm) * DK + n],       cc[0]);
        atomicAdd(&ctx[cb + (size_t)(wm + rm) * DK + n + 1],   cc[1]);
        atomicAdd(&ctx[cb + (size_t)(wm + rm + 8) * DK + n],   cc[2]);
        atomicAdd(&ctx[cb + (size_t)(wm + rm + 8) * DK + n+1], cc[3]);
    }
}

// ---- agg (tensorized): aggT[l, ch] = P[l,kk] · ctxn^T[kk,vv] ----------------
__global__ __launch_bounds__(256)
void agg_kernel(const __nv_bfloat16* __restrict__ qkvb, const float* __restrict__ ctx,
                const float* __restrict__ ksum, __nv_bfloat16* __restrict__ aggT) {
    __shared__ __nv_bfloat16 sP [128*CSTR];   // [l][kk]
    __shared__ __nv_bfloat16 sCt[64*CSTR];    // [vv][kk]
    __shared__ float sZ[64];
    int b = blockIdx.z, h = blockIdx.y, l0 = blockIdx.x * 128;
    int tid = threadIdx.x;
    int wid = tid >> 5, lane = tid & 31;

    if (tid < 64) sZ[tid] = 1.0f / ksum[b * Cn + h * DK + tid];
    __syncthreads();

    size_t cb = (size_t)(b * Hn + h) * DK * DK;
    for (int f = tid; f < 4096; f += 256) {
        int kk = f >> 6, vv = f & 63;
        sCt[vv * CSTR + kk] = __float2bfloat16_rn(ctx[cb + f] * sZ[kk]);
    }

    {
        int r = tid >> 1;
        int off = (tid & 1) * 32;
        const __nv_bfloat16* gq = qkvb + ((size_t)(b * Ln + l0 + r)) * QKV + h * DK + off;
        __nv_bfloat16 qv[32];
        *(uint4*)&qv[0]  = *(const uint4*)(gq);
        *(uint4*)&qv[8]  = *(const uint4*)(gq + 8);
        *(uint4*)&qv[16] = *(const uint4*)(gq + 16);
        *(uint4*)&qv[24] = *(const uint4*)(gq + 24);
        float e[32];
        float s = 0.f;
        #pragma unroll
        for (int j = 0; j < 32; j++) {
            e[j] = fexp(__bfloat162float(qv[j]));
            s += e[j];
        }
        s += __shfl_xor_sync(0xffffffffu, s, 1);
        float inv = 1.0f / s;
        __nv_bfloat16* pp = &sP[r * CSTR + off];
        #pragma unroll
        for (int j = 0; j < 32; j += 2)
            *(__nv_bfloat162*)(pp + j) = __floats2bfloat162_rn(e[j] * inv, e[j+1] * inv);
    }
    __syncthreads();

    int wm = (wid & 3) * 32, wn = (wid >> 2) * 32;
    int lrow = lane & 15, lko = (lane >> 4) * 16;
    uint32_t pb = smem_u32(sP), ctb = smem_u32(sCt);
    float acc[2][4][4] = {};
    #pragma unroll
    for (int ks = 0; ks < 4; ks++) {     // 4 k16 steps over kk
        uint32_t koff = (uint32_t)(ks * 32 + lko);
        uint32_t af[2][4], bf[2][4];
        #pragma unroll
        for (int mt = 0; mt < 2; mt++)
            ldsm4(af[mt], pb + (uint32_t)((wm + mt*16 + lrow) * CSTR * 2) + koff);
        #pragma unroll
        for (int g = 0; g < 2; g++)
            ldsm4(bf[g], ctb + (uint32_t)((wn + g*16 + lrow) * CSTR * 2) + koff);
        #pragma unroll
        for (int mt = 0; mt < 2; mt++)
            #pragma unroll
            for (int nt = 0; nt < 4; nt++) {
                uint32_t bb[2] = { bf[nt>>1][nt&1], bf[nt>>1][(nt&1) + 2] };
                mma_bf16(acc[mt][nt], af[mt], bb);
            }
    }

    int rm = lane >> 2, cnq = (lane & 3) * 2;
    #pragma unroll
    for (int mt = 0; mt < 2; mt++) {
        int l = wm + mt * 16 + rm;
        size_t ob0 = ((size_t)(b * Ln + l0 + l)) * Cn + h * DK;
        size_t ob1 = ((size_t)(b * Ln + l0 + l + 8)) * Cn + h * DK;
        #pragma unroll
        for (int nt = 0; nt < 4; nt++) {
            int n = wn + nt * 8 + cnq;
            float* cc = acc[mt][nt];
            *(__nv_bfloat162*)&aggT[ob0 + n] = __floats2bfloat162_rn(cc[0], cc[1]);
            *(__nv_bfloat162*)&aggT[ob1 + n] = __floats2bfloat162_rn(cc[2], cc[3]);
        }
    }
}

// ---------------- host launcher ---------------------------------------------
extern "C" void kernel_launch(void* const* d_in, const int* in_sizes, int n_in,
                              void* d_out, int out_size) {
    (void)in_sizes; (void)n_in; (void)out_size;
    const float* x     = (const float*)d_in[0];
    const float* v     = (const float*)d_in[1];
    const float* ln1_w = (const float*)d_in[4];
    const float* ln1_b = (const float*)d_in[5];
    const float* lnv_w = (const float*)d_in[6];
    const float* lnv_b = (const float*)d_in[7];
    const float* ln2_w = (const float*)d_in[8];
    const float* ln2_b = (const float*)d_in[9];
    const float* wq    = (const float*)d_in[10];
    const float* bq    = (const float*)d_in[11];
    const float* wk    = (const float*)d_in[12];
    const float* bk    = (const float*)d_in[13];
    const float* wv    = (const float*)d_in[14];
    const float* bv    = (const float*)d_in[15];
    const float* wr    = (const float*)d_in[16];
    const float* br    = (const float*)d_in[17];
    const float* fc1_w = (const float*)d_in[18];
    const float* fc1_b = (const float*)d_in[19];
    const float* fc2_w = (const float*)d_in[20];
    const float* fc2_b = (const float*)d_in[21];
    float* out = (float*)d_out;

    float *p_xnT, *p_ksum, *p_ctx, *p_x1, *p_bqkv;
    __nv_bfloat16 *p_xnb, *p_vnb, *p_qkvb, *p_aggT, *p_x1nb, *p_h1b;
    __nv_bfloat16 *p_wqkvb, *p_wrb, *p_f1b, *p_f2b;
    cudaGetSymbolAddress((void**)&p_xnT, g_xnT);
    cudaGetSymbolAddress((void**)&p_xnb, g_xnb);
    cudaGetSymbolAddress((void**)&p_vnb, g_vnb);
    cudaGetSymbolAddress((void**)&p_qkvb,g_qkvb);
    cudaGetSymbolAddress((void**)&p_ksum,g_ksum);
    cudaGetSymbolAddress((void**)&p_ctx, g_ctx);
    cudaGetSymbolAddress((void**)&p_aggT,g_aggT);
    cudaGetSymbolAddress((void**)&p_x1,  g_x1);
    cudaGetSymbolAddress((void**)&p_x1nb,g_x1nb);
    cudaGetSymbolAddress((void**)&p_h1b, g_h1b);
    cudaGetSymbolAddress((void**)&p_wqkvb,g_wqkvb);
    cudaGetSymbolAddress((void**)&p_wrb, g_wrb);
    cudaGetSymbolAddress((void**)&p_f1b, g_f1b);
    cudaGetSymbolAddress((void**)&p_f2b, g_f2b);
    cudaGetSymbolAddress((void**)&p_bqkv,g_bqkv);

    cudaFuncSetAttribute(gemm_bf16<1>, cudaFuncAttributeMaxDynamicSharedMemorySize, SMEM_REQ);
    cudaFuncSetAttribute(gemm_bf16<2>, cudaFuncAttributeMaxDynamicSharedMemorySize, SMEM_REQ);
    cudaFuncSetAttribute(gemm_bf16<6>, cudaFuncAttributeMaxDynamicSharedMemorySize, SMEM_REQ);
    cudaFuncSetAttribute(gemm_bf16<7>, cudaFuncAttributeMaxDynamicSharedMemorySize, SMEM_REQ);
    cudaFuncSetAttribute(ln_x_kernel, cudaFuncAttributeMaxDynamicSharedMemorySize, LNX_SMEM);

    // 0) fused prep: weight conversions + bias concat + ctx & ksum zero
    prep_kernel<<<(PREP_UNITS + 255)/256, 256>>>(wq, wk, wv, wr, fc1_w, fc2_w,
                                                 bq, bk, bv,
                                                 p_wqkvb, p_wrb, p_f1b, p_f2b,
                                                 p_bqkv, p_ctx, p_ksum);

    // 1) LN1(x) fused with transpose (-> xnb bf16 + xnT f32); LN(v) warp-per-row
    ln_x_kernel<<<Mrows / 32, 1024, LNX_SMEM>>>(x, ln1_w, ln1_b, p_xnb, p_xnT);
    ln_warp_kernel<<<Mrows / 32, 1024>>>(v, lnv_w, lnv_b, p_vnb);

    // 2) fused q|k|v projection (N=1536; A chosen per n-block)
    gemm_bf16<7><<<dim3(QKV / 128, Mrows / 128), 256, SMEM_REQ>>>(
        p_xnb, p_wqkvb, p_bqkv, (const float*)p_vnb, nullptr, p_qkvb, Mrows, QKV, Cn);

    // 3) context = sum_l exp(k)·val (unnormalized, tensorized) + ksum
    context_kernel<<<dim3(16, Hn, Bn), 256>>>(p_qkvb, p_ctx, p_ksum);

    // 4) aggT = softmax(q) @ (ctx/ksum)  -> (B, L, C) bf16 (tensorized)
    agg_kernel<<<dim3(Ln / 128, Hn, Bn), 256>>>(p_qkvb, p_ctx, p_ksum, p_aggT);

    // 5) reproj fused: x1 = wr·aggT + br + xnT + x
    gemm_bf16<6><<<dim3(Ln / 128, Cn / 128, Bn), 256, SMEM_REQ>>>(
        p_wrb, p_aggT, br, p_xnT, x, p_x1, Cn, Ln, Cn);

    // 6) x1n = LN(x1) (bf16, warp-per-row)
    ln_warp_kernel<<<Mrows / 32, 1024>>>(p_x1, ln2_w, ln2_b, p_x1nb);

    // 7) MLP
    gemm_bf16<1><<<dim3(HID / 128, Mrows / 128), 256, SMEM_REQ>>>(
        p_x1nb, p_f1b, fc1_b, nullptr, nullptr, p_h1b, Mrows, HID, Cn);
    gemm_bf16<2><<<dim3(Cn / 128, Mrows / 128), 256, SMEM_REQ>>>(
        p_h1b, p_f2b, fc2_b, p_x1, nullptr, out, Mrows, Cn, HID);
}